// round 5
// baseline (speedup 1.0000x reference)
#include <cuda_runtime.h>
#include <cstdint>

typedef unsigned long long u64;

#define Bb 32
#define Tt 512
#define Dd 512
#define Hh 1024
#define Gg 4096
#define Oo 512
#define NCTA 128

// ------------------------- persistent device state -------------------------
__device__ float g_XW[(size_t)Bb * Tt * Gg];      // x@Wx0+b0, row = b*Tt+t
__device__ float g_Y [(size_t)Bb * Tt * Hh];      // h1 sequence
__device__ float g_Wt0 [(size_t)Gg * Hh];         // Wh0^T  [G,K]
__device__ float g_Wt1x[(size_t)Gg * Hh];         // Wx1^T
__device__ float g_Wt1h[(size_t)Gg * Hh];         // Wh1^T
__device__ float g_h0[2][Bb * Hh];
__device__ float g_h1[2][Bb * Hh];
__device__ unsigned g_arrive[NCTA];
__device__ unsigned g_go;

// ------------------------- small helpers -----------------------------------
__device__ __forceinline__ void fma2(u64 &d, u64 a, u64 b) {
    asm volatile("fma.rn.f32x2 %0, %1, %2, %0;" : "+l"(d) : "l"(a), "l"(b));
}
__device__ __forceinline__ u64 splat2(float x) {
    u64 r; asm("mov.b64 %0, {%1, %1};" : "=l"(r) : "f"(x)); return r;
}
__device__ __forceinline__ float2 unpack2(u64 v) {
    float2 r; asm("mov.b64 {%0, %1}, %2;" : "=f"(r.x), "=f"(r.y) : "l"(v)); return r;
}
__device__ __forceinline__ void ld128_nc(ulonglong2 &r, const float* p) {
    asm("ld.global.nc.v2.u64 {%0,%1},[%2];" : "=l"(r.x), "=l"(r.y) : "l"(p));
}
__device__ __forceinline__ void ld128_cg(ulonglong2 &r, const float* p) {
    asm volatile("ld.global.cg.v2.u64 {%0,%1},[%2];" : "=l"(r.x), "=l"(r.y) : "l"(p));
}
__device__ __forceinline__ void st_rel(unsigned* p, unsigned v) {
    asm volatile("st.release.gpu.u32 [%0],%1;" :: "l"(p), "r"(v) : "memory");
}
__device__ __forceinline__ unsigned ld_acq(const unsigned* p) {
    unsigned v; asm volatile("ld.acquire.gpu.u32 %0,[%1];" : "=r"(v) : "l"(p) : "memory");
    return v;
}
__device__ __forceinline__ float sig_(float x) { return 1.f / (1.f + __expf(-x)); }
__device__ __forceinline__ float tanh_(float x) {
    float xx = fminf(fmaxf(x, -15.f), 15.f);
    float e = __expf(-2.f * xx);
    return (1.f - e) / (1.f + e);
}

// ------------------------- init ---------------------------------------------
__global__ void init_state() {
    int i = blockIdx.x * blockDim.x + threadIdx.x;
    if (i < Bb * Hh) {
        g_h0[0][i] = 0.f; g_h0[1][i] = 0.f;
        g_h1[0][i] = 0.f; g_h1[1][i] = 0.f;
    }
    if (i < NCTA) g_arrive[i] = 0;
    if (i == 0) g_go = 0;
}

// ------------------------- weight transpose [K=1024,G=4096] -> [G,K] --------
__global__ void transpose_w(const float* __restrict__ src, float* __restrict__ dst) {
    __shared__ float t[32][33];
    int bx = blockIdx.x * 32, by = blockIdx.y * 32;
    int x = threadIdx.x, y = threadIdx.y;
#pragma unroll
    for (int i = 0; i < 32; i += 8)
        t[y + i][x] = src[(size_t)(by + y + i) * Gg + bx + x];
    __syncthreads();
#pragma unroll
    for (int i = 0; i < 32; i += 8)
        dst[(size_t)(bx + y + i) * Hh + by + x] = t[x][y + i];
}

// ------------------------- GEMM: C = A[M,K]@B[K,N] + bias -------------------
// 128x64 tile, BK=16, 256 threads, 8x4 per-thread tile with f32x2.
__global__ void __launch_bounds__(256) sgemm_bias(
        const float* __restrict__ A, const float* __restrict__ Bm,
        const float* __restrict__ bias, float* __restrict__ C,
        int M, int N, int K)
{
    __shared__ float As[16][128];
    __shared__ float Bs[16][64];
    const int tid = threadIdx.x;
    const int bm = blockIdx.y * 128;
    const int bn = blockIdx.x * 64;
    const int tn = (tid & 15) * 4;
    const int tm = (tid >> 4) * 8;

    u64 acc[4][4];
#pragma unroll
    for (int i = 0; i < 4; ++i)
#pragma unroll
        for (int j = 0; j < 4; ++j) acc[i][j] = 0ULL;

    for (int k0 = 0; k0 < K; k0 += 16) {
#pragma unroll
        for (int i = 0; i < 2; ++i) {
            int fid = tid * 2 + i;
            int r = fid >> 2, kq = fid & 3;
            float4 v = *reinterpret_cast<const float4*>(A + (size_t)(bm + r) * K + k0 + kq * 4);
            As[kq * 4 + 0][r] = v.x;
            As[kq * 4 + 1][r] = v.y;
            As[kq * 4 + 2][r] = v.z;
            As[kq * 4 + 3][r] = v.w;
        }
        {
            int kr = tid >> 4, cq = (tid & 15) * 4;
            *reinterpret_cast<float4*>(&Bs[kr][cq]) =
                *reinterpret_cast<const float4*>(Bm + (size_t)(k0 + kr) * N + bn + cq);
        }
        __syncthreads();
#pragma unroll
        for (int kk = 0; kk < 16; ++kk) {
            ulonglong2 a01 = *reinterpret_cast<const ulonglong2*>(&As[kk][tm]);
            ulonglong2 a23 = *reinterpret_cast<const ulonglong2*>(&As[kk][tm + 4]);
            float4 bv = *reinterpret_cast<const float4*>(&Bs[kk][tn]);
            u64 bs0 = splat2(bv.x), bs1 = splat2(bv.y);
            u64 bs2 = splat2(bv.z), bs3 = splat2(bv.w);
            fma2(acc[0][0], a01.x, bs0); fma2(acc[0][1], a01.x, bs1);
            fma2(acc[0][2], a01.x, bs2); fma2(acc[0][3], a01.x, bs3);
            fma2(acc[1][0], a01.y, bs0); fma2(acc[1][1], a01.y, bs1);
            fma2(acc[1][2], a01.y, bs2); fma2(acc[1][3], a01.y, bs3);
            fma2(acc[2][0], a23.x, bs0); fma2(acc[2][1], a23.x, bs1);
            fma2(acc[2][2], a23.x, bs2); fma2(acc[2][3], a23.x, bs3);
            fma2(acc[3][0], a23.y, bs0); fma2(acc[3][1], a23.y, bs1);
            fma2(acc[3][2], a23.y, bs2); fma2(acc[3][3], a23.y, bs3);
        }
        __syncthreads();
    }

    float4 bb = *reinterpret_cast<const float4*>(bias + bn + tn);
#pragma unroll
    for (int mp = 0; mp < 4; ++mp) {
        float2 p0 = unpack2(acc[mp][0]);
        float2 p1 = unpack2(acc[mp][1]);
        float2 p2 = unpack2(acc[mp][2]);
        float2 p3 = unpack2(acc[mp][3]);
        int row0 = bm + tm + mp * 2;
        float4 o0 = make_float4(p0.x + bb.x, p1.x + bb.y, p2.x + bb.z, p3.x + bb.w);
        float4 o1 = make_float4(p0.y + bb.x, p1.y + bb.y, p2.y + bb.z, p3.y + bb.w);
        *reinterpret_cast<float4*>(C + (size_t)row0 * N + bn + tn) = o0;
        *reinterpret_cast<float4*>(C + (size_t)(row0 + 1) * N + bn + tn) = o1;
    }
}

// ------------------------- recurrence building blocks -----------------------
// acc[i][j]: col (c0i+i), batch (b0+j); pair dim = K. 128 k's per chunk.
__device__ __forceinline__ void mma_chunk(u64 (&acc)[4][4],
    const float* __restrict__ w0, const float* __restrict__ w1,
    const float* __restrict__ w2, const float* __restrict__ w3,
    const float* __restrict__ h0, const float* __restrict__ h1,
    const float* __restrict__ h2, const float* __restrict__ h3)
{
#pragma unroll 4
    for (int k = 0; k < 128; k += 4) {
        ulonglong2 wa, wb, wc, wd, ha, hb, hc, hd;
        ld128_nc(wa, w0 + k); ld128_nc(wb, w1 + k);
        ld128_nc(wc, w2 + k); ld128_nc(wd, w3 + k);
        ld128_cg(ha, h0 + k); ld128_cg(hb, h1 + k);
        ld128_cg(hc, h2 + k); ld128_cg(hd, h3 + k);
        fma2(acc[0][0], wa.x, ha.x); fma2(acc[0][0], wa.y, ha.y);
        fma2(acc[0][1], wa.x, hb.x); fma2(acc[0][1], wa.y, hb.y);
        fma2(acc[0][2], wa.x, hc.x); fma2(acc[0][2], wa.y, hc.y);
        fma2(acc[0][3], wa.x, hd.x); fma2(acc[0][3], wa.y, hd.y);
        fma2(acc[1][0], wb.x, ha.x); fma2(acc[1][0], wb.y, ha.y);
        fma2(acc[1][1], wb.x, hb.x); fma2(acc[1][1], wb.y, hb.y);
        fma2(acc[1][2], wb.x, hc.x); fma2(acc[1][2], wb.y, hc.y);
        fma2(acc[1][3], wb.x, hd.x); fma2(acc[1][3], wb.y, hd.y);
        fma2(acc[2][0], wc.x, ha.x); fma2(acc[2][0], wc.y, ha.y);
        fma2(acc[2][1], wc.x, hb.x); fma2(acc[2][1], wc.y, hb.y);
        fma2(acc[2][2], wc.x, hc.x); fma2(acc[2][2], wc.y, hc.y);
        fma2(acc[2][3], wc.x, hd.x); fma2(acc[2][3], wc.y, hd.y);
        fma2(acc[3][0], wd.x, ha.x); fma2(acc[3][0], wd.y, ha.y);
        fma2(acc[3][1], wd.x, hb.x); fma2(acc[3][1], wd.y, hb.y);
        fma2(acc[3][2], wd.x, hc.x); fma2(acc[3][2], wd.y, hc.y);
        fma2(acc[3][3], wd.x, hd.x); fma2(acc[3][3], wd.y, hd.y);
    }
}

__device__ __forceinline__ void store_red(float* red, u64 (&acc)[4][4],
                                          int kc, int c0i, int b0)
{
#pragma unroll
    for (int i = 0; i < 4; ++i) {
        float2 p0 = unpack2(acc[i][0]);
        float2 p1 = unpack2(acc[i][1]);
        float2 p2 = unpack2(acc[i][2]);
        float2 p3 = unpack2(acc[i][3]);
        float4 v = make_float4(p0.x + p0.y, p1.x + p1.y, p2.x + p2.y, p3.x + p3.y);
        *reinterpret_cast<float4*>(&red[kc * 1024 + (c0i + i) * 32 + b0]) = v;
    }
}

// flag-array grid barrier; target must be monotonically increasing
__device__ __forceinline__ void grid_bar(unsigned target) {
    __syncthreads();
    const unsigned tid = threadIdx.x;
    if (tid == 0) { __threadfence(); st_rel(&g_arrive[blockIdx.x], target); }
    if (blockIdx.x == 0) {
        if (tid < NCTA) { while (ld_acq(&g_arrive[tid]) < target) {} }
        __syncthreads();
        if (tid == 0) st_rel(&g_go, target);
    }
    if (tid == 0) { while (ld_acq(&g_go) < target) {} }
    __syncthreads();
}

// ------------------------- persistent 2-layer LSTM recurrence ---------------
// Interval s: layer0 step t=s (s<T) and layer1 step t=s-1 (s>0); both read
// h0(s-1). One grid sync per interval.
__global__ void __launch_bounds__(512, 1) lstm_rec(const float* __restrict__ b1)
{
    __shared__ float red[8 * 1024];   // 32 KB, red[kc][c][b]
    const int tid = threadIdx.x;
    const int kc = tid >> 6;          // 0..7, K chunk of 128
    const int ct = (tid >> 3) & 7;    // 4 cols
    const int bt = tid & 7;           // 4 batches
    const int c0i = ct * 4;
    const int b0 = bt * 4;
    const int jbase = blockIdx.x * 8;

    size_t wcol[4];
#pragma unroll
    for (int i = 0; i < 4; ++i) {
        int c = c0i + i;
        wcol[i] = (size_t)((c >> 3) * Hh + jbase + (c & 7)) * Hh + kc * 128;
    }

    const int gb = tid >> 3;  // gate thread: batch (tid < 256)
    const int gj = tid & 7;   // gate thread: local j
    float c0s = 0.f, c1s = 0.f;
    float bias1[4];
    if (tid < 256) {
#pragma unroll
        for (int g = 0; g < 4; ++g) bias1[g] = b1[g * Hh + jbase + gj];
    }

    for (int s = 0; s <= Tt; ++s) {
        const int rb = (s + 1) & 1;
        const int wb = s & 1;

        float xw[4];
        if (tid < 256 && s < Tt) {
#pragma unroll
            for (int g = 0; g < 4; ++g)
                xw[g] = __ldcg(&g_XW[((size_t)gb * Tt + s) * Gg + g * Hh + jbase + gj]);
        }

        // layer0 GEMM: h0(s-1) @ Wh0 (partials)
        if (s < Tt) {
            u64 acc[4][4];
#pragma unroll
            for (int i = 0; i < 4; ++i)
#pragma unroll
                for (int j = 0; j < 4; ++j) acc[i][j] = 0ULL;
            const float* hp = g_h0[rb];
            const int ko = kc * 128;
            mma_chunk(acc,
                g_Wt0 + wcol[0], g_Wt0 + wcol[1], g_Wt0 + wcol[2], g_Wt0 + wcol[3],
                hp + (b0 + 0) * Hh + ko, hp + (b0 + 1) * Hh + ko,
                hp + (b0 + 2) * Hh + ko, hp + (b0 + 3) * Hh + ko);
            store_red(red, acc, kc, c0i, b0);
        }
        __syncthreads();

        // gate threads pull z0 into registers (red gets reused by layer1)
        float z0[4];
        if (tid < 256 && s < Tt) {
#pragma unroll
            for (int g = 0; g < 4; ++g) {
                float t = xw[g];
#pragma unroll
                for (int kk = 0; kk < 8; ++kk)
                    t += red[kk * 1024 + (g * 8 + gj) * 32 + gb];
                z0[g] = t;
            }
        }
        __syncthreads();

        // layer1 GEMM: h0(s-1) @ Wx1 + h1(s-2) @ Wh1 (partials)
        if (s > 0) {
            u64 acc[4][4];
#pragma unroll
            for (int i = 0; i < 4; ++i)
#pragma unroll
                for (int j = 0; j < 4; ++j) acc[i][j] = 0ULL;
            const float* ha = g_h0[rb];
            const float* hc = g_h1[rb];
            const int ko = kc * 128;
            mma_chunk(acc,
                g_Wt1x + wcol[0], g_Wt1x + wcol[1], g_Wt1x + wcol[2], g_Wt1x + wcol[3],
                ha + (b0 + 0) * Hh + ko, ha + (b0 + 1) * Hh + ko,
                ha + (b0 + 2) * Hh + ko, ha + (b0 + 3) * Hh + ko);
            mma_chunk(acc,
                g_Wt1h + wcol[0], g_Wt1h + wcol[1], g_Wt1h + wcol[2], g_Wt1h + wcol[3],
                hc + (b0 + 0) * Hh + ko, hc + (b0 + 1) * Hh + ko,
                hc + (b0 + 2) * Hh + ko, hc + (b0 + 3) * Hh + ko);
            store_red(red, acc, kc, c0i, b0);
        }
        __syncthreads();

        // gates
        if (tid < 256) {
            if (s < Tt) {
                float ci = sig_(z0[0]), cf = sig_(z0[1]);
                float cg = tanh_(z0[2]), co = sig_(z0[3]);
                c0s = cf * c0s + ci * cg;
                g_h0[wb][gb * Hh + jbase + gj] = co * tanh_(c0s);
            }
            if (s > 0) {
                float z1[4];
#pragma unroll
                for (int g = 0; g < 4; ++g) {
                    float t = bias1[g];
#pragma unroll
                    for (int kk = 0; kk < 8; ++kk)
                        t += red[kk * 1024 + (g * 8 + gj) * 32 + gb];
                    z1[g] = t;
                }
                float ci = sig_(z1[0]), cf = sig_(z1[1]);
                float cg = tanh_(z1[2]), co = sig_(z1[3]);
                c1s = cf * c1s + ci * cg;
                float hn = co * tanh_(c1s);
                g_h1[wb][gb * Hh + jbase + gj] = hn;
                g_Y[((size_t)gb * Tt + (s - 1)) * Hh + jbase + gj] = hn;
            }
        }
        grid_bar((unsigned)(s + 1));
    }
}

// ------------------------- launch --------------------------------------------
extern "C" void kernel_launch(void* const* d_in, const int* in_sizes, int n_in,
                              void* d_out, int out_size)
{
    const float* x   = (const float*)d_in[0];
    const float* Wx0 = (const float*)d_in[1];
    const float* Wh0 = (const float*)d_in[2];
    // b0 folded into XW via sgemm bias: d_in[3]
    const float* b0v = (const float*)d_in[3];
    const float* Wx1 = (const float*)d_in[4];
    const float* Wh1 = (const float*)d_in[5];
    const float* b1v = (const float*)d_in[6];
    const float* Wd  = (const float*)d_in[7];
    const float* bdv = (const float*)d_in[8];
    float* out = (float*)d_out;

    float* xw;  cudaGetSymbolAddress((void**)&xw,  g_XW);
    float* yv;  cudaGetSymbolAddress((void**)&yv,  g_Y);
    float* wt0; cudaGetSymbolAddress((void**)&wt0, g_Wt0);
    float* wt1x; cudaGetSymbolAddress((void**)&wt1x, g_Wt1x);
    float* wt1h; cudaGetSymbolAddress((void**)&wt1h, g_Wt1h);

    init_state<<<64, 512>>>();
    dim3 tb(32, 8), tg(Gg / 32, Hh / 32);
    transpose_w<<<tg, tb>>>(Wh0, wt0);
    transpose_w<<<tg, tb>>>(Wx1, wt1x);
    transpose_w<<<tg, tb>>>(Wh1, wt1h);

    // XW = x @ Wx0 + b0   [16384, 4096]
    sgemm_bias<<<dim3(Gg / 64, (Bb * Tt) / 128), 256>>>(x, Wx0, b0v, xw,
                                                        Bb * Tt, Gg, Dd);
    // recurrence
    lstm_rec<<<NCTA, 512>>>(b1v);

    // out = Y @ Wd + bd   [16384, 512]
    sgemm_bias<<<dim3(Oo / 64, (Bb * Tt) / 128), 256>>>(yv, Wd, bdv, out,
                                                        Bb * Tt, Oo, Hh);
}

// round 7
// speedup vs baseline: 2.8926x; 2.8926x over previous
#include <cuda_runtime.h>
#include <cstdint>

typedef unsigned long long u64;

#define Bb 32
#define Tt 512
#define Dd 512
#define Hh 1024
#define Gg 4096
#define Oo 512
#define NCTA 128
#define PKTOT 12582912   // 128cta * 3mat * 8kc * 2cth * 2048 floats

__device__ float g_XW[(size_t)Bb * Tt * Gg];
__device__ float g_Y [(size_t)Bb * Tt * Hh];
__device__ float g_Wpk[(size_t)PKTOT];
__device__ float g_h0[2][Bb * Hh];
__device__ float g_h1[2][Bb * Hh];
__device__ unsigned g_arrive[NCTA];
__device__ unsigned g_go;

__device__ __forceinline__ void fma2(u64 &d, u64 a, u64 b) {
    asm volatile("fma.rn.f32x2 %0, %1, %2, %0;" : "+l"(d) : "l"(a), "l"(b));
}
__device__ __forceinline__ u64 splat2(float x) {
    u64 r; asm("mov.b64 %0, {%1, %1};" : "=l"(r) : "f"(x)); return r;
}
__device__ __forceinline__ float2 unpack2(u64 v) {
    float2 r; asm("mov.b64 {%0, %1}, %2;" : "=f"(r.x), "=f"(r.y) : "l"(v)); return r;
}
__device__ __forceinline__ ulonglong2 ldg128(const float4* p) {
    ulonglong2 r;
    asm("ld.global.nc.v2.u64 {%0,%1},[%2];" : "=l"(r.x), "=l"(r.y) : "l"(p));
    return r;
}
__device__ __forceinline__ ulonglong2 lds128(unsigned a) {
    ulonglong2 r;
    asm volatile("ld.shared.v2.u64 {%0,%1},[%2];" : "=l"(r.x), "=l"(r.y) : "r"(a));
    return r;
}
__device__ __forceinline__ void sts128(unsigned a, float4 v) {
    asm volatile("st.shared.v4.b32 [%0],{%1,%2,%3,%4};"
                 :: "r"(a), "f"(v.x), "f"(v.y), "f"(v.z), "f"(v.w));
}
__device__ __forceinline__ unsigned smem_u32(const void* p) {
    unsigned a;
    asm("{ .reg .u64 t; cvta.to.shared.u64 t, %1; cvt.u32.u64 %0, t; }"
        : "=r"(a) : "l"(p));
    return a;
}
__device__ __forceinline__ void st_rel(unsigned* p, unsigned v) {
    asm volatile("st.release.gpu.u32 [%0],%1;" :: "l"(p), "r"(v) : "memory");
}
__device__ __forceinline__ unsigned ld_acq(const unsigned* p) {
    unsigned v; asm volatile("ld.acquire.gpu.u32 %0,[%1];" : "=r"(v) : "l"(p) : "memory");
    return v;
}
__device__ __forceinline__ float sig_(float x) { return 1.f / (1.f + __expf(-x)); }
__device__ __forceinline__ float tanh_(float x) {
    float xx = fminf(fmaxf(x, -15.f), 15.f);
    float e = __expf(-2.f * xx);
    return (1.f - e) / (1.f + e);
}

__global__ void init_state() {
    int i = blockIdx.x * blockDim.x + threadIdx.x;
    if (i < Bb * Hh) {
        g_h0[0][i] = 0.f; g_h0[1][i] = 0.f;
        g_h1[0][i] = 0.f; g_h1[1][i] = 0.f;
    }
    if (i < NCTA) g_arrive[i] = 0;
    if (i == 0) g_go = 0;
}

// pack layout (float idx within warp region of 2048):
//   k4(2b) | ct3(2b) | i(2b) | q(5b);  region = ((cta*3+mat)*8+kc)*2+cth
__global__ void pack_w(const float* __restrict__ W0, const float* __restrict__ W1,
                       const float* __restrict__ W2)
{
    size_t idx = (size_t)blockIdx.x * blockDim.x + threadIdx.x;
    int k4 = idx & 3, ct3 = (idx >> 2) & 3, i = (idx >> 4) & 3, q = (idx >> 6) & 31;
    int cth = (idx >> 11) & 1, kc = (idx >> 12) & 7;
    int mc = (int)(idx >> 15);
    int mat = mc % 3, cta = mc / 3;
    int c = (cth * 4 + ct3) * 4 + i;
    int gcol = (c >> 3) * Hh + cta * 8 + (c & 7);
    int k = kc * 128 + q * 4 + k4;
    const float* W = (mat == 0) ? W0 : ((mat == 1) ? W1 : W2);
    g_Wpk[idx] = W[(size_t)k * Gg + gcol];
}

// ---------------- GEMM: C = A[M,K]@B[K,N] + bias ----------------------------
__global__ void __launch_bounds__(256) sgemm_bias(
        const float* __restrict__ A, const float* __restrict__ Bm,
        const float* __restrict__ bias, float* __restrict__ C,
        int M, int N, int K)
{
    __shared__ float As[16][128];
    __shared__ float Bs[16][64];
    const int tid = threadIdx.x;
    const int bm = blockIdx.y * 128;
    const int bn = blockIdx.x * 64;
    const int tn = (tid & 15) * 4;
    const int tm = (tid >> 4) * 8;

    u64 acc[4][4];
#pragma unroll
    for (int i = 0; i < 4; ++i)
#pragma unroll
        for (int j = 0; j < 4; ++j) acc[i][j] = 0ULL;

    for (int k0 = 0; k0 < K; k0 += 16) {
#pragma unroll
        for (int i = 0; i < 2; ++i) {
            int fid = tid * 2 + i;
            int r = fid >> 2, kq = fid & 3;
            float4 v = *reinterpret_cast<const float4*>(A + (size_t)(bm + r) * K + k0 + kq * 4);
            As[kq * 4 + 0][r] = v.x;
            As[kq * 4 + 1][r] = v.y;
            As[kq * 4 + 2][r] = v.z;
            As[kq * 4 + 3][r] = v.w;
        }
        {
            int kr = tid >> 4, cq = (tid & 15) * 4;
            *reinterpret_cast<float4*>(&Bs[kr][cq]) =
                *reinterpret_cast<const float4*>(Bm + (size_t)(k0 + kr) * N + bn + cq);
        }
        __syncthreads();
#pragma unroll
        for (int kk = 0; kk < 16; ++kk) {
            ulonglong2 a01 = *reinterpret_cast<const ulonglong2*>(&As[kk][tm]);
            ulonglong2 a23 = *reinterpret_cast<const ulonglong2*>(&As[kk][tm + 4]);
            float4 bv = *reinterpret_cast<const float4*>(&Bs[kk][tn]);
            u64 bs0 = splat2(bv.x), bs1 = splat2(bv.y);
            u64 bs2 = splat2(bv.z), bs3 = splat2(bv.w);
            fma2(acc[0][0], a01.x, bs0); fma2(acc[0][1], a01.x, bs1);
            fma2(acc[0][2], a01.x, bs2); fma2(acc[0][3], a01.x, bs3);
            fma2(acc[1][0], a01.y, bs0); fma2(acc[1][1], a01.y, bs1);
            fma2(acc[1][2], a01.y, bs2); fma2(acc[1][3], a01.y, bs3);
            fma2(acc[2][0], a23.x, bs0); fma2(acc[2][1], a23.x, bs1);
            fma2(acc[2][2], a23.x, bs2); fma2(acc[2][3], a23.x, bs3);
            fma2(acc[3][0], a23.y, bs0); fma2(acc[3][1], a23.y, bs1);
            fma2(acc[3][2], a23.y, bs2); fma2(acc[3][3], a23.y, bs3);
        }
        __syncthreads();
    }

    float4 bb = *reinterpret_cast<const float4*>(bias + bn + tn);
#pragma unroll
    for (int mp = 0; mp < 4; ++mp) {
        float2 p0 = unpack2(acc[mp][0]);
        float2 p1 = unpack2(acc[mp][1]);
        float2 p2 = unpack2(acc[mp][2]);
        float2 p3 = unpack2(acc[mp][3]);
        int row0 = bm + tm + mp * 2;
        float4 o0 = make_float4(p0.x + bb.x, p1.x + bb.y, p2.x + bb.z, p3.x + bb.w);
        float4 o1 = make_float4(p0.y + bb.x, p1.y + bb.y, p2.y + bb.z, p3.y + bb.w);
        *reinterpret_cast<float4*>(C + (size_t)row0 * N + bn + tn) = o0;
        *reinterpret_cast<float4*>(C + (size_t)(row0 + 1) * N + bn + tn) = o1;
    }
}

// ---------------- recurrence pieces ------------------------------------------
// hs: 32 rows x 4KB, quad swizzle q' = q ^ ((b>>2)&7)
__device__ __forceinline__ void stage_h(unsigned hsb, const float* __restrict__ src,
                                        int tid)
{
    const float4* s4 = reinterpret_cast<const float4*>(src);
#pragma unroll
    for (int ii = 0; ii < 16; ++ii) {
        int i4 = tid + ii * 512;
        float4 v = __ldcg(s4 + i4);
        int b = i4 >> 8, q = i4 & 255;
        unsigned off = (unsigned)(b * 4096 + ((q ^ ((b >> 2) & 7)) << 4));
        sts128(hsb + off, v);
    }
}

// one 128-k chunk of one matrix; hrow is an ABSOLUTE smem address (hsb included)
__device__ __forceinline__ void mma(u64 (&a)[4][4], const float4* __restrict__ pw,
                                    unsigned hrow, int qh0, int bt)
{
#pragma unroll 4
    for (int q = 0; q < 32; ++q) {
        ulonglong2 w0 = ldg128(pw + q * 16 + 0);
        ulonglong2 w1 = ldg128(pw + q * 16 + 4);
        ulonglong2 w2 = ldg128(pw + q * 16 + 8);
        ulonglong2 w3 = ldg128(pw + q * 16 + 12);
        unsigned off = hrow + (unsigned)((qh0 + (q ^ bt)) << 4);
        ulonglong2 h0 = lds128(off);
        ulonglong2 h1 = lds128(off + 4096);
        ulonglong2 h2 = lds128(off + 8192);
        ulonglong2 h3 = lds128(off + 12288);
        fma2(a[0][0], w0.x, h0.x); fma2(a[0][0], w0.y, h0.y);
        fma2(a[0][1], w0.x, h1.x); fma2(a[0][1], w0.y, h1.y);
        fma2(a[0][2], w0.x, h2.x); fma2(a[0][2], w0.y, h2.y);
        fma2(a[0][3], w0.x, h3.x); fma2(a[0][3], w0.y, h3.y);
        fma2(a[1][0], w1.x, h0.x); fma2(a[1][0], w1.y, h0.y);
        fma2(a[1][1], w1.x, h1.x); fma2(a[1][1], w1.y, h1.y);
        fma2(a[1][2], w1.x, h2.x); fma2(a[1][2], w1.y, h2.y);
        fma2(a[1][3], w1.x, h3.x); fma2(a[1][3], w1.y, h3.y);
        fma2(a[2][0], w2.x, h0.x); fma2(a[2][0], w2.y, h0.y);
        fma2(a[2][1], w2.x, h1.x); fma2(a[2][1], w2.y, h1.y);
        fma2(a[2][2], w2.x, h2.x); fma2(a[2][2], w2.y, h2.y);
        fma2(a[2][3], w2.x, h3.x); fma2(a[2][3], w2.y, h3.y);
        fma2(a[3][0], w3.x, h0.x); fma2(a[3][0], w3.y, h0.y);
        fma2(a[3][1], w3.x, h1.x); fma2(a[3][1], w3.y, h1.y);
        fma2(a[3][2], w3.x, h2.x); fma2(a[3][2], w3.y, h2.y);
        fma2(a[3][3], w3.x, h3.x); fma2(a[3][3], w3.y, h3.y);
    }
}

__device__ __forceinline__ void store_red(float* red, u64 (&acc)[4][4],
                                          int kc, int c0i, int b0)
{
#pragma unroll
    for (int i = 0; i < 4; ++i) {
        float2 p0 = unpack2(acc[i][0]);
        float2 p1 = unpack2(acc[i][1]);
        float2 p2 = unpack2(acc[i][2]);
        float2 p3 = unpack2(acc[i][3]);
        float4 v = make_float4(p0.x + p0.y, p1.x + p1.y, p2.x + p2.y, p3.x + p3.y);
        *reinterpret_cast<float4*>(&red[kc * 1024 + (c0i + i) * 32 + b0]) = v;
    }
}

__device__ __forceinline__ void grid_bar(unsigned target) {
    __syncthreads();
    const unsigned tid = threadIdx.x;
    if (tid == 0) { __threadfence(); st_rel(&g_arrive[blockIdx.x], target); }
    if (blockIdx.x == 0) {
        if (tid < NCTA) { while (ld_acq(&g_arrive[tid]) < target) {} }
        __syncthreads();
        if (tid == 0) st_rel(&g_go, target);
    }
    if (tid == 0) { while (ld_acq(&g_go) < target) {} }
    __syncthreads();
}

// ---------------- persistent 2-layer LSTM recurrence -------------------------
__global__ void __launch_bounds__(512, 1) lstm_rec2(const float* __restrict__ b1)
{
    extern __shared__ float smem[];
    float* red = smem + 32768;                 // after 128KB hs
    const unsigned hsb = smem_u32(smem);

    const int tid = threadIdx.x;
    const int lane = tid & 31;
    const int kc = tid >> 6;
    const int cth = (tid >> 5) & 1;
    const int ct3 = lane >> 3;
    const int bt = lane & 7;
    const int c0i = (cth * 4 + ct3) * 4;
    const int b0 = bt * 4;
    const int cta = blockIdx.x;
    const int jbase = cta * 8;
    const int qh0 = kc * 32;
    const unsigned hrow = hsb + (unsigned)(b0 * 4096);   // FIX: include smem base

    const float4* pw0 = reinterpret_cast<const float4*>(
        g_Wpk + ((((size_t)cta * 3 + 0) * 8 + kc) * 2 + cth) * 2048) + ct3;
    const float4* pw1 = pw0 + 8192;   // +8*2*2048 floats
    const float4* pw2 = pw0 + 16384;

    const int gb = tid >> 3;
    const int gj = tid & 7;
    float c0s = 0.f, c1s = 0.f;
    float bias1[4];
    if (tid < 256) {
#pragma unroll
        for (int g = 0; g < 4; ++g) bias1[g] = b1[g * Hh + jbase + gj];
    }

    for (int s = 0; s <= Tt; ++s) {
        const int rb = (s + 1) & 1;
        const int wb = s & 1;

        stage_h(hsb, g_h0[rb], tid);
        __syncthreads();

        float xw[4];
        if (tid < 256 && s < Tt) {
#pragma unroll
            for (int g = 0; g < 4; ++g)
                xw[g] = __ldcg(&g_XW[((size_t)gb * Tt + s) * Gg + g * Hh + jbase + gj]);
        }

        if (s < Tt) {
            u64 acc[4][4];
#pragma unroll
            for (int i = 0; i < 4; ++i)
#pragma unroll
                for (int j = 0; j < 4; ++j) acc[i][j] = 0ULL;
            mma(acc, pw0, hrow, qh0, bt);
            store_red(red, acc, kc, c0i, b0);
        }
        __syncthreads();

        float z0[4];
        if (tid < 256 && s < Tt) {
#pragma unroll
            for (int g = 0; g < 4; ++g) {
                float t = xw[g];
#pragma unroll
                for (int kk = 0; kk < 8; ++kk)
                    t += red[kk * 1024 + (g * 8 + gj) * 32 + gb];
                z0[g] = t;
            }
        }
        __syncthreads();

        u64 accB[4][4];
        if (s > 0) {
#pragma unroll
            for (int i = 0; i < 4; ++i)
#pragma unroll
                for (int j = 0; j < 4; ++j) accB[i][j] = 0ULL;
            mma(accB, pw1, hrow, qh0, bt);     // Wx1 x h0 (hs holds h0)
        }
        __syncthreads();                       // all done reading hs(h0)

        stage_h(hsb, g_h1[rb], tid);           // hs := h1(s-2)
        __syncthreads();

        if (s > 0) {
            mma(accB, pw2, hrow, qh0, bt);     // + Wh1 x h1
            store_red(red, accB, kc, c0i, b0);
        }
        __syncthreads();

        if (tid < 256) {
            if (s < Tt) {
                float ci = sig_(z0[0]), cf = sig_(z0[1]);
                float cg = tanh_(z0[2]), co = sig_(z0[3]);
                c0s = cf * c0s + ci * cg;
                g_h0[wb][gb * Hh + jbase + gj] = co * tanh_(c0s);
            }
            if (s > 0) {
                float z1[4];
#pragma unroll
                for (int g = 0; g < 4; ++g) {
                    float t = bias1[g];
#pragma unroll
                    for (int kk = 0; kk < 8; ++kk)
                        t += red[kk * 1024 + (g * 8 + gj) * 32 + gb];
                    z1[g] = t;
                }
                float ci = sig_(z1[0]), cf = sig_(z1[1]);
                float cg = tanh_(z1[2]), co = sig_(z1[3]);
                c1s = cf * c1s + ci * cg;
                float hn = co * tanh_(c1s);
                g_h1[wb][gb * Hh + jbase + gj] = hn;
                g_Y[((size_t)gb * Tt + (s - 1)) * Hh + jbase + gj] = hn;
            }
        }
        grid_bar((unsigned)(s + 1));
    }
}

// ---------------- launch ------------------------------------------------------
extern "C" void kernel_launch(void* const* d_in, const int* in_sizes, int n_in,
                              void* d_out, int out_size)
{
    const float* x   = (const float*)d_in[0];
    const float* Wx0 = (const float*)d_in[1];
    const float* Wh0 = (const float*)d_in[2];
    const float* b0v = (const float*)d_in[3];
    const float* Wx1 = (const float*)d_in[4];
    const float* Wh1 = (const float*)d_in[5];
    const float* b1v = (const float*)d_in[6];
    const float* Wd  = (const float*)d_in[7];
    const float* bdv = (const float*)d_in[8];
    float* out = (float*)d_out;

    float* xw; cudaGetSymbolAddress((void**)&xw, g_XW);
    float* yv; cudaGetSymbolAddress((void**)&yv, g_Y);

    cudaFuncSetAttribute(lstm_rec2,
                         cudaFuncAttributeMaxDynamicSharedMemorySize, 163840);

    init_state<<<64, 512>>>();
    pack_w<<<PKTOT / 256, 256>>>(Wh0, Wx1, Wh1);

    sgemm_bias<<<dim3(Gg / 64, (Bb * Tt) / 128), 256>>>(x, Wx0, b0v, xw,
                                                        Bb * Tt, Gg, Dd);
    lstm_rec2<<<NCTA, 512, 163840>>>(b1v);

    sgemm_bias<<<dim3(Oo / 64, (Bb * Tt) / 128), 256>>>(yv, Wd, bdv, out,
                                                        Bb * Tt, Oo, Hh);
}

// round 8
// speedup vs baseline: 3.7060x; 1.2812x over previous
#include <cuda_runtime.h>
#include <cstdint>

typedef unsigned long long u64;

#define Bb 32
#define Tt 512
#define Dd 512
#define Hh 1024
#define Gg 4096
#define Oo 512
#define NCTA 128
#define PKTOT 12582912
#define SMEMB 217088

__device__ float g_XW[(size_t)Bb * Tt * Gg];
__device__ float g_Y [(size_t)Bb * Tt * Hh];
__device__ float g_Wpk[(size_t)PKTOT];
__device__ float g_h0[2][Bb * Hh];
__device__ float g_h1[2][Bb * Hh];
__device__ unsigned g_arrive[NCTA];
__device__ unsigned g_go;

__device__ __forceinline__ void fma2(u64 &d, u64 a, u64 b) {
    asm volatile("fma.rn.f32x2 %0, %1, %2, %0;" : "+l"(d) : "l"(a), "l"(b));
}
__device__ __forceinline__ u64 splat2(float x) {
    u64 r; asm("mov.b64 %0, {%1, %1};" : "=l"(r) : "f"(x)); return r;
}
__device__ __forceinline__ float2 unpack2(u64 v) {
    float2 r; asm("mov.b64 {%0, %1}, %2;" : "=f"(r.x), "=f"(r.y) : "l"(v)); return r;
}
__device__ __forceinline__ ulonglong2 lds128(unsigned a) {
    ulonglong2 r;
    asm volatile("ld.shared.v2.u64 {%0,%1},[%2];" : "=l"(r.x), "=l"(r.y) : "r"(a));
    return r;
}
__device__ __forceinline__ void sts128(unsigned a, float4 v) {
    asm volatile("st.shared.v4.b32 [%0],{%1,%2,%3,%4};"
                 :: "r"(a), "f"(v.x), "f"(v.y), "f"(v.z), "f"(v.w));
}
__device__ __forceinline__ unsigned smem_u32(const void* p) {
    unsigned a;
    asm("{ .reg .u64 t; cvta.to.shared.u64 t, %1; cvt.u32.u64 %0, t; }"
        : "=r"(a) : "l"(p));
    return a;
}
__device__ __forceinline__ void st_rel(unsigned* p, unsigned v) {
    asm volatile("st.release.gpu.u32 [%0],%1;" :: "l"(p), "r"(v) : "memory");
}
__device__ __forceinline__ unsigned ld_acq(const unsigned* p) {
    unsigned v; asm volatile("ld.acquire.gpu.u32 %0,[%1];" : "=r"(v) : "l"(p) : "memory");
    return v;
}
// prefetch one 1KB W block (256 floats) into smem; one commit group
__device__ __forceinline__ void wpf(unsigned dst, const float* src, int lane) {
    asm volatile("cp.async.cg.shared.global [%0],[%1],16;\n\t"
                 "cp.async.cg.shared.global [%2],[%3],16;\n\t"
                 "cp.async.commit_group;"
                 :: "r"(dst + lane * 16), "l"(src + lane * 4),
                    "r"(dst + 512 + lane * 16), "l"(src + 128 + lane * 4)
                 : "memory");
}
__device__ __forceinline__ void wwait1() {
    asm volatile("cp.async.wait_group 1;" ::: "memory");
}
__device__ __forceinline__ float sig_(float x) { return 1.f / (1.f + __expf(-x)); }
__device__ __forceinline__ float tanh_(float x) {
    float xx = fminf(fmaxf(x, -15.f), 15.f);
    float e = __expf(-2.f * xx);
    return (1.f - e) / (1.f + e);
}

__global__ void init_state() {
    int i = blockIdx.x * blockDim.x + threadIdx.x;
    if (i < Bb * Hh) {
        g_h0[0][i] = 0.f; g_h0[1][i] = 0.f;
        g_h1[0][i] = 0.f; g_h1[1][i] = 0.f;
    }
    if (i < NCTA) g_arrive[i] = 0;
    if (i == 0) g_go = 0;
}

// pack layout: float idx in region = q*64 + i*16 + ct3*4 + k4
// region = ((cta*3+mat)*8+kc)*2+cth, 2048 floats each
__global__ void pack_w(const float* __restrict__ W0, const float* __restrict__ W1,
                       const float* __restrict__ W2)
{
    size_t idx = (size_t)blockIdx.x * blockDim.x + threadIdx.x;
    int k4 = idx & 3, ct3 = (idx >> 2) & 3, i = (idx >> 4) & 3, q = (idx >> 6) & 31;
    int cth = (idx >> 11) & 1, kc = (idx >> 12) & 7;
    int mc = (int)(idx >> 15);
    int mat = mc % 3, cta = mc / 3;
    int c = (cth * 4 + ct3) * 4 + i;
    int gcol = (c >> 3) * Hh + cta * 8 + (c & 7);
    int k = kc * 128 + q * 4 + k4;
    const float* W = (mat == 0) ? W0 : ((mat == 1) ? W1 : W2);
    g_Wpk[idx] = W[(size_t)k * Gg + gcol];
}

// ---------------- GEMM: C = A[M,K]@B[K,N] + bias ----------------------------
__global__ void __launch_bounds__(256) sgemm_bias(
        const float* __restrict__ A, const float* __restrict__ Bm,
        const float* __restrict__ bias, float* __restrict__ C,
        int M, int N, int K)
{
    __shared__ float As[16][128];
    __shared__ float Bs[16][64];
    const int tid = threadIdx.x;
    const int bm = blockIdx.y * 128;
    const int bn = blockIdx.x * 64;
    const int tn = (tid & 15) * 4;
    const int tm = (tid >> 4) * 8;

    u64 acc[4][4];
#pragma unroll
    for (int i = 0; i < 4; ++i)
#pragma unroll
        for (int j = 0; j < 4; ++j) acc[i][j] = 0ULL;

    for (int k0 = 0; k0 < K; k0 += 16) {
#pragma unroll
        for (int i = 0; i < 2; ++i) {
            int fid = tid * 2 + i;
            int r = fid >> 2, kq = fid & 3;
            float4 v = *reinterpret_cast<const float4*>(A + (size_t)(bm + r) * K + k0 + kq * 4);
            As[kq * 4 + 0][r] = v.x;
            As[kq * 4 + 1][r] = v.y;
            As[kq * 4 + 2][r] = v.z;
            As[kq * 4 + 3][r] = v.w;
        }
        {
            int kr = tid >> 4, cq = (tid & 15) * 4;
            *reinterpret_cast<float4*>(&Bs[kr][cq]) =
                *reinterpret_cast<const float4*>(Bm + (size_t)(k0 + kr) * N + bn + cq);
        }
        __syncthreads();
#pragma unroll
        for (int kk = 0; kk < 16; ++kk) {
            ulonglong2 a01 = *reinterpret_cast<const ulonglong2*>(&As[kk][tm]);
            ulonglong2 a23 = *reinterpret_cast<const ulonglong2*>(&As[kk][tm + 4]);
            float4 bv = *reinterpret_cast<const float4*>(&Bs[kk][tn]);
            u64 bs0 = splat2(bv.x), bs1 = splat2(bv.y);
            u64 bs2 = splat2(bv.z), bs3 = splat2(bv.w);
            fma2(acc[0][0], a01.x, bs0); fma2(acc[0][1], a01.x, bs1);
            fma2(acc[0][2], a01.x, bs2); fma2(acc[0][3], a01.x, bs3);
            fma2(acc[1][0], a01.y, bs0); fma2(acc[1][1], a01.y, bs1);
            fma2(acc[1][2], a01.y, bs2); fma2(acc[1][3], a01.y, bs3);
            fma2(acc[2][0], a23.x, bs0); fma2(acc[2][1], a23.x, bs1);
            fma2(acc[2][2], a23.x, bs2); fma2(acc[2][3], a23.x, bs3);
            fma2(acc[3][0], a23.y, bs0); fma2(acc[3][1], a23.y, bs1);
            fma2(acc[3][2], a23.y, bs2); fma2(acc[3][3], a23.y, bs3);
        }
        __syncthreads();
    }

    float4 bb = *reinterpret_cast<const float4*>(bias + bn + tn);
#pragma unroll
    for (int mp = 0; mp < 4; ++mp) {
        float2 p0 = unpack2(acc[mp][0]);
        float2 p1 = unpack2(acc[mp][1]);
        float2 p2 = unpack2(acc[mp][2]);
        float2 p3 = unpack2(acc[mp][3]);
        int row0 = bm + tm + mp * 2;
        float4 o0 = make_float4(p0.x + bb.x, p1.x + bb.y, p2.x + bb.z, p3.x + bb.w);
        float4 o1 = make_float4(p0.y + bb.x, p1.y + bb.y, p2.y + bb.z, p3.y + bb.w);
        *reinterpret_cast<float4*>(C + (size_t)row0 * N + bn + tn) = o0;
        *reinterpret_cast<float4*>(C + (size_t)(row0 + 1) * N + bn + tn) = o1;
    }
}

// ---------------- recurrence pieces ------------------------------------------
__device__ __forceinline__ void stage_h(unsigned hsb, const float* __restrict__ src,
                                        int tid)
{
    const float4* s4 = reinterpret_cast<const float4*>(src);
#pragma unroll
    for (int ii = 0; ii < 16; ++ii) {
        int i4 = tid + ii * 512;
        float4 v = __ldcg(s4 + i4);
        int b = i4 >> 8, q = i4 & 255;
        unsigned off = (unsigned)(b * 4096 + ((q ^ ((b >> 2) & 7)) << 4));
        sts128(hsb + off, v);
    }
}

// 4 q-iters from one 1KB W slot; all-smem operands
__device__ __forceinline__ void mma4(u64 (&a)[4][4], unsigned wslot, unsigned hrow,
                                     int qh0, int q0, int bt, int ct3)
{
#pragma unroll
    for (int qin = 0; qin < 4; ++qin) {
        unsigned wq = wslot + (unsigned)(qin * 256 + ct3 * 16);
        ulonglong2 w0 = lds128(wq);
        ulonglong2 w1 = lds128(wq + 64);
        ulonglong2 w2 = lds128(wq + 128);
        ulonglong2 w3 = lds128(wq + 192);
        unsigned off = hrow + (unsigned)((qh0 + ((q0 + qin) ^ bt)) << 4);
        ulonglong2 h0 = lds128(off);
        ulonglong2 h1 = lds128(off + 4096);
        ulonglong2 h2 = lds128(off + 8192);
        ulonglong2 h3 = lds128(off + 12288);
        fma2(a[0][0], w0.x, h0.x); fma2(a[0][0], w0.y, h0.y);
        fma2(a[0][1], w0.x, h1.x); fma2(a[0][1], w0.y, h1.y);
        fma2(a[0][2], w0.x, h2.x); fma2(a[0][2], w0.y, h2.y);
        fma2(a[0][3], w0.x, h3.x); fma2(a[0][3], w0.y, h3.y);
        fma2(a[1][0], w1.x, h0.x); fma2(a[1][0], w1.y, h0.y);
        fma2(a[1][1], w1.x, h1.x); fma2(a[1][1], w1.y, h1.y);
        fma2(a[1][2], w1.x, h2.x); fma2(a[1][2], w1.y, h2.y);
        fma2(a[1][3], w1.x, h3.x); fma2(a[1][3], w1.y, h3.y);
        fma2(a[2][0], w2.x, h0.x); fma2(a[2][0], w2.y, h0.y);
        fma2(a[2][1], w2.x, h1.x); fma2(a[2][1], w2.y, h1.y);
        fma2(a[2][2], w2.x, h2.x); fma2(a[2][2], w2.y, h2.y);
        fma2(a[2][3], w2.x, h3.x); fma2(a[2][3], w2.y, h3.y);
        fma2(a[3][0], w3.x, h0.x); fma2(a[3][0], w3.y, h0.y);
        fma2(a[3][1], w3.x, h1.x); fma2(a[3][1], w3.y, h1.y);
        fma2(a[3][2], w3.x, h2.x); fma2(a[3][2], w3.y, h2.y);
        fma2(a[3][3], w3.x, h3.x); fma2(a[3][3], w3.y, h3.y);
    }
}

// one matrix = 8 blocks of the per-warp 24-block stream (ring of 3 slots)
__device__ __forceinline__ void run_mat(u64 (&acc)[4][4], bool active, int &cb,
    unsigned wring, const float* __restrict__ wg, unsigned hrow,
    int qh0, int bt, int ct3, int lane)
{
#pragma unroll 1
    for (int blk = 0; blk < 8; ++blk) {
        wwait1();
        __syncwarp();
        if (active)
            mma4(acc, wring + (unsigned)((cb % 3) * 1024), hrow, qh0, blk * 4, bt, ct3);
        __syncwarp();
        int pb = cb + 2; if (pb >= 24) pb -= 24;
        wpf(wring + (unsigned)((pb % 3) * 1024),
            wg + (size_t)(pb >> 3) * 32768 + (pb & 7) * 256, lane);
        ++cb; if (cb >= 24) cb = 0;
    }
}

// red stride: c rows padded to 36 words (conflict-free gate reads)
__device__ __forceinline__ void store_red(float* red, u64 (&acc)[4][4],
                                          int kc, int c0i, int b0)
{
#pragma unroll
    for (int i = 0; i < 4; ++i) {
        float2 p0 = unpack2(acc[i][0]);
        float2 p1 = unpack2(acc[i][1]);
        float2 p2 = unpack2(acc[i][2]);
        float2 p3 = unpack2(acc[i][3]);
        float4 v = make_float4(p0.x + p0.y, p1.x + p1.y, p2.x + p2.y, p3.x + p3.y);
        *reinterpret_cast<float4*>(&red[kc * 1152 + (c0i + i) * 36 + b0]) = v;
    }
}

__device__ __forceinline__ void grid_bar(unsigned target) {
    __syncthreads();
    const unsigned tid = threadIdx.x;
    if (tid == 0) { __threadfence(); st_rel(&g_arrive[blockIdx.x], target); }
    if (blockIdx.x == 0) {
        if (tid < NCTA) { while (ld_acq(&g_arrive[tid]) < target) {} }
        __syncthreads();
        if (tid == 0) st_rel(&g_go, target);
    }
    if (tid == 0) { while (ld_acq(&g_go) < target) {} }
    __syncthreads();
}

// ---------------- persistent 2-layer LSTM recurrence -------------------------
__global__ void __launch_bounds__(512, 1) lstm_rec3(const float* __restrict__ b1)
{
    extern __shared__ float smem[];
    float* red = smem + 32768;                       // 36KB after 128KB hs
    const unsigned hsb = smem_u32(smem);

    const int tid = threadIdx.x;
    const int lane = tid & 31;
    const int wid = tid >> 5;
    const int kc = tid >> 6;
    const int cth = (tid >> 5) & 1;
    const int ct3 = lane >> 3;
    const int bt = lane & 7;
    const int c0i = (cth * 4 + ct3) * 4;
    const int b0 = bt * 4;
    const int cta = blockIdx.x;
    const int jbase = cta * 8;
    const int qh0 = kc * 32;
    const unsigned hrow = hsb + (unsigned)(b0 * 4096);
    const unsigned wring = hsb + 167936u + (unsigned)(wid * 3072);
    const float* wg = g_Wpk + ((((size_t)cta * 3 + 0) * 8 + kc) * 2 + cth) * 2048;

    const int gb = tid >> 3;
    const int gj = tid & 7;
    float c0s = 0.f, c1s = 0.f;
    float bias1[4];
    if (tid < 256) {
#pragma unroll
        for (int g = 0; g < 4; ++g) bias1[g] = b1[g * Hh + jbase + gj];
    }

    // warm up W stream: blocks 0,1 -> slots 0,1
    int cb = 0;
    wpf(wring, wg, lane);
    wpf(wring + 1024, wg + 256, lane);

    for (int s = 0; s <= Tt; ++s) {
        const int rb = (s + 1) & 1;
        const int wb = s & 1;

        stage_h(hsb, g_h0[rb], tid);
        __syncthreads();

        float xw[4];
        if (tid < 256 && s < Tt) {
#pragma unroll
            for (int g = 0; g < 4; ++g)
                xw[g] = __ldcg(&g_XW[((size_t)gb * Tt + s) * Gg + g * Hh + jbase + gj]);
        }

        u64 acc[4][4];
#pragma unroll
        for (int i = 0; i < 4; ++i)
#pragma unroll
            for (int j = 0; j < 4; ++j) acc[i][j] = 0ULL;
        run_mat(acc, s < Tt, cb, wring, wg, hrow, qh0, bt, ct3, lane);  // Wh0 x h0
        if (s < Tt) store_red(red, acc, kc, c0i, b0);
        __syncthreads();

        float z0[4];
        if (tid < 256 && s < Tt) {
#pragma unroll
            for (int g = 0; g < 4; ++g) {
                float t = xw[g];
#pragma unroll
                for (int kk = 0; kk < 8; ++kk)
                    t += red[kk * 1152 + (g * 8 + gj) * 36 + gb];
                z0[g] = t;
            }
        }
        __syncthreads();

        u64 accB[4][4];
#pragma unroll
        for (int i = 0; i < 4; ++i)
#pragma unroll
            for (int j = 0; j < 4; ++j) accB[i][j] = 0ULL;
        run_mat(accB, s > 0, cb, wring, wg, hrow, qh0, bt, ct3, lane);  // Wx1 x h0
        __syncthreads();

        stage_h(hsb, g_h1[rb], tid);                                   // hs := h1(s-2)
        __syncthreads();

        run_mat(accB, s > 0, cb, wring, wg, hrow, qh0, bt, ct3, lane);  // + Wh1 x h1
        if (s > 0) store_red(red, accB, kc, c0i, b0);
        __syncthreads();

        if (tid < 256) {
            if (s < Tt) {
                float ci = sig_(z0[0]), cf = sig_(z0[1]);
                float cg = tanh_(z0[2]), co = sig_(z0[3]);
                c0s = cf * c0s + ci * cg;
                g_h0[wb][gb * Hh + jbase + gj] = co * tanh_(c0s);
            }
            if (s > 0) {
                float z1[4];
#pragma unroll
                for (int g = 0; g < 4; ++g) {
                    float t = bias1[g];
#pragma unroll
                    for (int kk = 0; kk < 8; ++kk)
                        t += red[kk * 1152 + (g * 8 + gj) * 36 + gb];
                    z1[g] = t;
                }
                float ci = sig_(z1[0]), cf = sig_(z1[1]);
                float cg = tanh_(z1[2]), co = sig_(z1[3]);
                c1s = cf * c1s + ci * cg;
                float hn = co * tanh_(c1s);
                g_h1[wb][gb * Hh + jbase + gj] = hn;
                g_Y[((size_t)gb * Tt + (s - 1)) * Hh + jbase + gj] = hn;
            }
        }
        grid_bar((unsigned)(s + 1));
    }
    asm volatile("cp.async.wait_group 0;" ::: "memory");
}

// ---------------- launch ------------------------------------------------------
extern "C" void kernel_launch(void* const* d_in, const int* in_sizes, int n_in,
                              void* d_out, int out_size)
{
    const float* x   = (const float*)d_in[0];
    const float* Wx0 = (const float*)d_in[1];
    const float* Wh0 = (const float*)d_in[2];
    const float* b0v = (const float*)d_in[3];
    const float* Wx1 = (const float*)d_in[4];
    const float* Wh1 = (const float*)d_in[5];
    const float* b1v = (const float*)d_in[6];
    const float* Wd  = (const float*)d_in[7];
    const float* bdv = (const float*)d_in[8];
    float* out = (float*)d_out;

    float* xw; cudaGetSymbolAddress((void**)&xw, g_XW);
    float* yv; cudaGetSymbolAddress((void**)&yv, g_Y);

    cudaFuncSetAttribute(lstm_rec3,
                         cudaFuncAttributeMaxDynamicSharedMemorySize, SMEMB);

    init_state<<<64, 512>>>();
    pack_w<<<PKTOT / 256, 256>>>(Wh0, Wx1, Wh1);

    sgemm_bias<<<dim3(Gg / 64, (Bb * Tt) / 128), 256>>>(x, Wx0, b0v, xw,
                                                        Bb * Tt, Gg, Dd);
    lstm_rec3<<<NCTA, 512, SMEMB>>>(b1v);

    sgemm_bias<<<dim3(Oo / 64, (Bb * Tt) / 128), 256>>>(yv, Wd, bdv, out,
                                                        Bb * Tt, Oo, Hh);
}

// round 9
// speedup vs baseline: 3.7209x; 1.0040x over previous
#include <cuda_runtime.h>
#include <cstdint>

typedef unsigned long long u64;

#define Bb 32
#define Tt 512
#define Dd 512
#define Hh 1024
#define Gg 4096
#define Oo 512
#define NCTA 128
#define PKTOT 12582912
#define SMEMB 217088

__device__ float g_XW[(size_t)Bb * Tt * Gg];
__device__ float g_Y [(size_t)Bb * Tt * Hh];
__device__ float g_Wpk[(size_t)PKTOT];
__device__ float g_h0[2][Bb * Hh];
__device__ float g_h1[2][Bb * Hh];
__device__ unsigned g_arrive[NCTA];
__device__ unsigned g_go;

__device__ __forceinline__ void fma2(u64 &d, u64 a, u64 b) {
    asm volatile("fma.rn.f32x2 %0, %1, %2, %0;" : "+l"(d) : "l"(a), "l"(b));
}
__device__ __forceinline__ u64 splat2(float x) {
    u64 r; asm("mov.b64 %0, {%1, %1};" : "=l"(r) : "f"(x)); return r;
}
__device__ __forceinline__ float2 unpack2(u64 v) {
    float2 r; asm("mov.b64 {%0, %1}, %2;" : "=f"(r.x), "=f"(r.y) : "l"(v)); return r;
}
__device__ __forceinline__ ulonglong2 lds128(unsigned a) {
    ulonglong2 r;
    asm volatile("ld.shared.v2.u64 {%0,%1},[%2];" : "=l"(r.x), "=l"(r.y) : "r"(a));
    return r;
}
__device__ __forceinline__ void sts128(unsigned a, float4 v) {
    asm volatile("st.shared.v4.b32 [%0],{%1,%2,%3,%4};"
                 :: "r"(a), "f"(v.x), "f"(v.y), "f"(v.z), "f"(v.w));
}
__device__ __forceinline__ unsigned smem_u32(const void* p) {
    unsigned a;
    asm("{ .reg .u64 t; cvta.to.shared.u64 t, %1; cvt.u32.u64 %0, t; }"
        : "=r"(a) : "l"(p));
    return a;
}
__device__ __forceinline__ void st_rel(unsigned* p, unsigned v) {
    asm volatile("st.release.gpu.u32 [%0],%1;" :: "l"(p), "r"(v) : "memory");
}
__device__ __forceinline__ unsigned ld_acq(const unsigned* p) {
    unsigned v; asm volatile("ld.acquire.gpu.u32 %0,[%1];" : "=r"(v) : "l"(p) : "memory");
    return v;
}
// prefetch one 1KB W block (256 floats) into smem; one commit group
__device__ __forceinline__ void wpf(unsigned dst, const float* src, int lane) {
    asm volatile("cp.async.cg.shared.global [%0],[%1],16;\n\t"
                 "cp.async.cg.shared.global [%2],[%3],16;\n\t"
                 "cp.async.commit_group;"
                 :: "r"(dst + lane * 16), "l"(src + lane * 4),
                    "r"(dst + 512 + lane * 16), "l"(src + 128 + lane * 4)
                 : "memory");
}
__device__ __forceinline__ void wwait2() {
    asm volatile("cp.async.wait_group 2;" ::: "memory");
}
__device__ __forceinline__ float sig_(float x) { return 1.f / (1.f + __expf(-x)); }
__device__ __forceinline__ float tanh_(float x) {
    float xx = fminf(fmaxf(x, -15.f), 15.f);
    float e = __expf(-2.f * xx);
    return (1.f - e) / (1.f + e);
}

__global__ void init_state() {
    int i = blockIdx.x * blockDim.x + threadIdx.x;
    if (i < Bb * Hh) {
        g_h0[0][i] = 0.f; g_h0[1][i] = 0.f;
        g_h1[0][i] = 0.f; g_h1[1][i] = 0.f;
    }
    if (i < NCTA) g_arrive[i] = 0;
    if (i == 0) g_go = 0;
}

// pack layout: float idx in region = q*64 + i*16 + ct3*4 + k4
// region = ((cta*3+mat)*8+kc)*2+cth, 2048 floats each
__global__ void pack_w(const float* __restrict__ W0, const float* __restrict__ W1,
                       const float* __restrict__ W2)
{
    size_t idx = (size_t)blockIdx.x * blockDim.x + threadIdx.x;
    int k4 = idx & 3, ct3 = (idx >> 2) & 3, i = (idx >> 4) & 3, q = (idx >> 6) & 31;
    int cth = (idx >> 11) & 1, kc = (idx >> 12) & 7;
    int mc = (int)(idx >> 15);
    int mat = mc % 3, cta = mc / 3;
    int c = (cth * 4 + ct3) * 4 + i;
    int gcol = (c >> 3) * Hh + cta * 8 + (c & 7);
    int k = kc * 128 + q * 4 + k4;
    const float* W = (mat == 0) ? W0 : ((mat == 1) ? W1 : W2);
    g_Wpk[idx] = W[(size_t)k * Gg + gcol];
}

// ---------------- GEMM: C = A[M,K]@B[K,N] + bias ----------------------------
__global__ void __launch_bounds__(256) sgemm_bias(
        const float* __restrict__ A, const float* __restrict__ Bm,
        const float* __restrict__ bias, float* __restrict__ C,
        int M, int N, int K)
{
    __shared__ float As[16][128];
    __shared__ float Bs[16][64];
    const int tid = threadIdx.x;
    const int bm = blockIdx.y * 128;
    const int bn = blockIdx.x * 64;
    const int tn = (tid & 15) * 4;
    const int tm = (tid >> 4) * 8;

    u64 acc[4][4];
#pragma unroll
    for (int i = 0; i < 4; ++i)
#pragma unroll
        for (int j = 0; j < 4; ++j) acc[i][j] = 0ULL;

    for (int k0 = 0; k0 < K; k0 += 16) {
#pragma unroll
        for (int i = 0; i < 2; ++i) {
            int fid = tid * 2 + i;
            int r = fid >> 2, kq = fid & 3;
            float4 v = *reinterpret_cast<const float4*>(A + (size_t)(bm + r) * K + k0 + kq * 4);
            As[kq * 4 + 0][r] = v.x;
            As[kq * 4 + 1][r] = v.y;
            As[kq * 4 + 2][r] = v.z;
            As[kq * 4 + 3][r] = v.w;
        }
        {
            int kr = tid >> 4, cq = (tid & 15) * 4;
            *reinterpret_cast<float4*>(&Bs[kr][cq]) =
                *reinterpret_cast<const float4*>(Bm + (size_t)(k0 + kr) * N + bn + cq);
        }
        __syncthreads();
#pragma unroll
        for (int kk = 0; kk < 16; ++kk) {
            ulonglong2 a01 = *reinterpret_cast<const ulonglong2*>(&As[kk][tm]);
            ulonglong2 a23 = *reinterpret_cast<const ulonglong2*>(&As[kk][tm + 4]);
            float4 bv = *reinterpret_cast<const float4*>(&Bs[kk][tn]);
            u64 bs0 = splat2(bv.x), bs1 = splat2(bv.y);
            u64 bs2 = splat2(bv.z), bs3 = splat2(bv.w);
            fma2(acc[0][0], a01.x, bs0); fma2(acc[0][1], a01.x, bs1);
            fma2(acc[0][2], a01.x, bs2); fma2(acc[0][3], a01.x, bs3);
            fma2(acc[1][0], a01.y, bs0); fma2(acc[1][1], a01.y, bs1);
            fma2(acc[1][2], a01.y, bs2); fma2(acc[1][3], a01.y, bs3);
            fma2(acc[2][0], a23.x, bs0); fma2(acc[2][1], a23.x, bs1);
            fma2(acc[2][2], a23.x, bs2); fma2(acc[2][3], a23.x, bs3);
            fma2(acc[3][0], a23.y, bs0); fma2(acc[3][1], a23.y, bs1);
            fma2(acc[3][2], a23.y, bs2); fma2(acc[3][3], a23.y, bs3);
        }
        __syncthreads();
    }

    float4 bb = *reinterpret_cast<const float4*>(bias + bn + tn);
#pragma unroll
    for (int mp = 0; mp < 4; ++mp) {
        float2 p0 = unpack2(acc[mp][0]);
        float2 p1 = unpack2(acc[mp][1]);
        float2 p2 = unpack2(acc[mp][2]);
        float2 p3 = unpack2(acc[mp][3]);
        int row0 = bm + tm + mp * 2;
        float4 o0 = make_float4(p0.x + bb.x, p1.x + bb.y, p2.x + bb.z, p3.x + bb.w);
        float4 o1 = make_float4(p0.y + bb.x, p1.y + bb.y, p2.y + bb.z, p3.y + bb.w);
        *reinterpret_cast<float4*>(C + (size_t)row0 * N + bn + tn) = o0;
        *reinterpret_cast<float4*>(C + (size_t)(row0 + 1) * N + bn + tn) = o1;
    }
}

// ---------------- recurrence pieces ------------------------------------------
__device__ __forceinline__ void stage_h(unsigned hsb, const float* __restrict__ src,
                                        int tid)
{
    const float4* s4 = reinterpret_cast<const float4*>(src);
#pragma unroll
    for (int ii = 0; ii < 16; ++ii) {
        int i4 = tid + ii * 512;
        float4 v = __ldcg(s4 + i4);
        int b = i4 >> 8, q = i4 & 255;
        unsigned off = (unsigned)(b * 4096 + ((q ^ ((b >> 2) & 7)) << 4));
        sts128(hsb + off, v);
    }
}

#define FMA32(w0,w1,w2,w3,h0,h1,h2,h3)                              \
    fma2(a[0][0], w0.x, h0.x); fma2(a[0][0], w0.y, h0.y);           \
    fma2(a[0][1], w0.x, h1.x); fma2(a[0][1], w0.y, h1.y);           \
    fma2(a[0][2], w0.x, h2.x); fma2(a[0][2], w0.y, h2.y);           \
    fma2(a[0][3], w0.x, h3.x); fma2(a[0][3], w0.y, h3.y);           \
    fma2(a[1][0], w1.x, h0.x); fma2(a[1][0], w1.y, h0.y);           \
    fma2(a[1][1], w1.x, h1.x); fma2(a[1][1], w1.y, h1.y);           \
    fma2(a[1][2], w1.x, h2.x); fma2(a[1][2], w1.y, h2.y);           \
    fma2(a[1][3], w1.x, h3.x); fma2(a[1][3], w1.y, h3.y);           \
    fma2(a[2][0], w2.x, h0.x); fma2(a[2][0], w2.y, h0.y);           \
    fma2(a[2][1], w2.x, h1.x); fma2(a[2][1], w2.y, h1.y);           \
    fma2(a[2][2], w2.x, h2.x); fma2(a[2][2], w2.y, h2.y);           \
    fma2(a[2][3], w2.x, h3.x); fma2(a[2][3], w2.y, h3.y);           \
    fma2(a[3][0], w3.x, h0.x); fma2(a[3][0], w3.y, h0.y);           \
    fma2(a[3][1], w3.x, h1.x); fma2(a[3][1], w3.y, h1.y);           \
    fma2(a[3][2], w3.x, h2.x); fma2(a[3][2], w3.y, h2.y);           \
    fma2(a[3][3], w3.x, h3.x); fma2(a[3][3], w3.y, h3.y)

// 4 q-iters from one 1KB W slot; software-pipelined (preload q+1 during q FMAs)
__device__ __forceinline__ void mma4(u64 (&a)[4][4], unsigned wslot, unsigned hrow,
                                     int qh0, int q0, int bt, int ct3)
{
    unsigned wq = wslot + (unsigned)(ct3 * 16);
    ulonglong2 w0 = lds128(wq), w1 = lds128(wq + 64),
               w2 = lds128(wq + 128), w3 = lds128(wq + 192);
    unsigned off = hrow + (unsigned)((qh0 + (q0 ^ bt)) << 4);
    ulonglong2 h0 = lds128(off), h1 = lds128(off + 4096),
               h2 = lds128(off + 8192), h3 = lds128(off + 12288);
#pragma unroll
    for (int qin = 0; qin < 4; ++qin) {
        ulonglong2 nw0, nw1, nw2, nw3, nh0, nh1, nh2, nh3;
        if (qin < 3) {
            unsigned wq2 = wslot + (unsigned)((qin + 1) * 256 + ct3 * 16);
            nw0 = lds128(wq2);       nw1 = lds128(wq2 + 64);
            nw2 = lds128(wq2 + 128); nw3 = lds128(wq2 + 192);
            unsigned off2 = hrow + (unsigned)((qh0 + ((q0 + qin + 1) ^ bt)) << 4);
            nh0 = lds128(off2);        nh1 = lds128(off2 + 4096);
            nh2 = lds128(off2 + 8192); nh3 = lds128(off2 + 12288);
        }
        FMA32(w0, w1, w2, w3, h0, h1, h2, h3);
        if (qin < 3) {
            w0 = nw0; w1 = nw1; w2 = nw2; w3 = nw3;
            h0 = nh0; h1 = nh1; h2 = nh2; h3 = nh3;
        }
    }
}

// one matrix = 8 blocks; prefetch block n+2 BEFORE computing n (depth-2 in flight)
__device__ __forceinline__ void run_mat(u64 (&acc)[4][4], bool active, int &cb,
    unsigned wring, const float* __restrict__ wg, unsigned hrow,
    int qh0, int bt, int ct3, int lane)
{
#pragma unroll 1
    for (int blk = 0; blk < 8; ++blk) {
        int pb = cb + 2; if (pb >= 24) pb -= 24;
        wpf(wring + (unsigned)((pb % 3) * 1024),
            wg + (size_t)(pb >> 3) * 32768 + (pb & 7) * 256, lane);
        wwait2();
        __syncwarp();
        if (active)
            mma4(acc, wring + (unsigned)((cb % 3) * 1024), hrow, qh0, blk * 4, bt, ct3);
        ++cb; if (cb >= 24) cb = 0;
    }
}

// red stride: c rows padded to 36 words (conflict-free gate reads)
__device__ __forceinline__ void store_red(float* red, u64 (&acc)[4][4],
                                          int kc, int c0i, int b0)
{
#pragma unroll
    for (int i = 0; i < 4; ++i) {
        float2 p0 = unpack2(acc[i][0]);
        float2 p1 = unpack2(acc[i][1]);
        float2 p2 = unpack2(acc[i][2]);
        float2 p3 = unpack2(acc[i][3]);
        float4 v = make_float4(p0.x + p0.y, p1.x + p1.y, p2.x + p2.y, p3.x + p3.y);
        *reinterpret_cast<float4*>(&red[kc * 1152 + (c0i + i) * 36 + b0]) = v;
    }
}

__device__ __forceinline__ void grid_bar(unsigned target) {
    __syncthreads();
    const unsigned tid = threadIdx.x;
    if (tid == 0) { __threadfence(); st_rel(&g_arrive[blockIdx.x], target); }
    if (blockIdx.x == 0) {
        if (tid < NCTA) { while (ld_acq(&g_arrive[tid]) < target) {} }
        __syncthreads();
        if (tid == 0) st_rel(&g_go, target);
    }
    if (tid == 0) { while (ld_acq(&g_go) < target) {} }
    __syncthreads();
}

// ---------------- persistent 2-layer LSTM recurrence -------------------------
__global__ void __launch_bounds__(512, 1) lstm_rec4(const float* __restrict__ b1)
{
    extern __shared__ float smem[];
    float* red = smem + 32768;                       // 36KB after 128KB hs
    const unsigned hsb = smem_u32(smem);

    const int tid = threadIdx.x;
    const int lane = tid & 31;
    const int wid = tid >> 5;
    const int kc = tid >> 6;
    const int cth = (tid >> 5) & 1;
    const int ct3 = lane >> 3;
    const int bt = lane & 7;
    const int c0i = (cth * 4 + ct3) * 4;
    const int b0 = bt * 4;
    const int cta = blockIdx.x;
    const int jbase = cta * 8;
    const int qh0 = kc * 32;
    const unsigned hrow = hsb + (unsigned)(b0 * 4096);
    const unsigned wring = hsb + 167936u + (unsigned)(wid * 3072);
    const float* wg = g_Wpk + ((((size_t)cta * 3 + 0) * 8 + kc) * 2 + cth) * 2048;

    const int gb = tid >> 3;
    const int gj = tid & 7;
    float c0s = 0.f, c1s = 0.f;
    float bias1[4];
    if (tid < 256) {
#pragma unroll
        for (int g = 0; g < 4; ++g) bias1[g] = b1[g * Hh + jbase + gj];
    }

    // warm up W stream: blocks 0,1 -> slots 0,1
    int cb = 0;
    wpf(wring, wg, lane);
    wpf(wring + 1024, wg + 256, lane);

    for (int s = 0; s <= Tt; ++s) {
        const int rb = (s + 1) & 1;
        const int wb = s & 1;

        stage_h(hsb, g_h0[rb], tid);
        __syncthreads();

        float xw[4];
        if (tid < 256 && s < Tt) {
#pragma unroll
            for (int g = 0; g < 4; ++g)
                xw[g] = __ldcg(&g_XW[((size_t)gb * Tt + s) * Gg + g * Hh + jbase + gj]);
        }

        u64 acc[4][4];
#pragma unroll
        for (int i = 0; i < 4; ++i)
#pragma unroll
            for (int j = 0; j < 4; ++j) acc[i][j] = 0ULL;
        run_mat(acc, s < Tt, cb, wring, wg, hrow, qh0, bt, ct3, lane);  // Wh0 x h0
        if (s < Tt) store_red(red, acc, kc, c0i, b0);
        __syncthreads();

        float z0[4];
        if (tid < 256 && s < Tt) {
#pragma unroll
            for (int g = 0; g < 4; ++g) {
                float t = xw[g];
#pragma unroll
                for (int kk = 0; kk < 8; ++kk)
                    t += red[kk * 1152 + (g * 8 + gj) * 36 + gb];
                z0[g] = t;
            }
        }
        __syncthreads();

        u64 accB[4][4];
#pragma unroll
        for (int i = 0; i < 4; ++i)
#pragma unroll
            for (int j = 0; j < 4; ++j) accB[i][j] = 0ULL;
        run_mat(accB, s > 0, cb, wring, wg, hrow, qh0, bt, ct3, lane);  // Wx1 x h0
        __syncthreads();

        stage_h(hsb, g_h1[rb], tid);                                   // hs := h1(s-2)
        __syncthreads();

        run_mat(accB, s > 0, cb, wring, wg, hrow, qh0, bt, ct3, lane);  // + Wh1 x h1
        if (s > 0) store_red(red, accB, kc, c0i, b0);
        __syncthreads();

        if (tid < 256) {
            if (s < Tt) {
                float ci = sig_(z0[0]), cf = sig_(z0[1]);
                float cg = tanh_(z0[2]), co = sig_(z0[3]);
                c0s = cf * c0s + ci * cg;
                g_h0[wb][gb * Hh + jbase + gj] = co * tanh_(c0s);
            }
            if (s > 0) {
                float z1[4];
#pragma unroll
                for (int g = 0; g < 4; ++g) {
                    float t = bias1[g];
#pragma unroll
                    for (int kk = 0; kk < 8; ++kk)
                        t += red[kk * 1152 + (g * 8 + gj) * 36 + gb];
                    z1[g] = t;
                }
                float ci = sig_(z1[0]), cf = sig_(z1[1]);
                float cg = tanh_(z1[2]), co = sig_(z1[3]);
                c1s = cf * c1s + ci * cg;
                float hn = co * tanh_(c1s);
                g_h1[wb][gb * Hh + jbase + gj] = hn;
                g_Y[((size_t)gb * Tt + (s - 1)) * Hh + jbase + gj] = hn;
            }
        }
        grid_bar((unsigned)(s + 1));
    }
    asm volatile("cp.async.wait_group 0;" ::: "memory");
}

// ---------------- launch ------------------------------------------------------
extern "C" void kernel_launch(void* const* d_in, const int* in_sizes, int n_in,
                              void* d_out, int out_size)
{
    const float* x   = (const float*)d_in[0];
    const float* Wx0 = (const float*)d_in[1];
    const float* Wh0 = (const float*)d_in[2];
    const float* b0v = (const float*)d_in[3];
    const float* Wx1 = (const float*)d_in[4];
    const float* Wh1 = (const float*)d_in[5];
    const float* b1v = (const float*)d_in[6];
    const float* Wd  = (const float*)d_in[7];
    const float* bdv = (const float*)d_in[8];
    float* out = (float*)d_out;

    float* xw; cudaGetSymbolAddress((void**)&xw, g_XW);
    float* yv; cudaGetSymbolAddress((void**)&yv, g_Y);

    cudaFuncSetAttribute(lstm_rec4,
                         cudaFuncAttributeMaxDynamicSharedMemorySize, SMEMB);

    init_state<<<64, 512>>>();
    pack_w<<<PKTOT / 256, 256>>>(Wh0, Wx1, Wh1);

    sgemm_bias<<<dim3(Gg / 64, (Bb * Tt) / 128), 256>>>(x, Wx0, b0v, xw,
                                                        Bb * Tt, Gg, Dd);
    lstm_rec4<<<NCTA, 512, SMEMB>>>(b1v);

    sgemm_bias<<<dim3(Oo / 64, (Bb * Tt) / 128), 256>>>(yv, Wd, bdv, out,
                                                        Bb * Tt, Oo, Hh);
}

// round 10
// speedup vs baseline: 3.7549x; 1.0091x over previous
#include <cuda_runtime.h>
#include <cstdint>

typedef unsigned long long u64;

#define Bb 32
#define Tt 512
#define Dd 512
#define Hh 1024
#define Gg 4096
#define Oo 512
#define NCTA 128
#define PKTOT 12582912
#define SMEMB 217088

__device__ float g_XW[(size_t)Bb * Tt * Gg];
__device__ float g_Y [(size_t)Bb * Tt * Hh];
__device__ float g_Wpk[(size_t)PKTOT];
__device__ float g_h0[2][Bb * Hh];
__device__ float g_h1[2][Bb * Hh];
__device__ unsigned g_arrive[NCTA];
__device__ unsigned g_go;

__device__ __forceinline__ void fma2(u64 &d, u64 a, u64 b) {
    asm volatile("fma.rn.f32x2 %0, %1, %2, %0;" : "+l"(d) : "l"(a), "l"(b));
}
__device__ __forceinline__ u64 splat2(float x) {
    u64 r; asm("mov.b64 %0, {%1, %1};" : "=l"(r) : "f"(x)); return r;
}
__device__ __forceinline__ float2 unpack2(u64 v) {
    float2 r; asm("mov.b64 {%0, %1}, %2;" : "=f"(r.x), "=f"(r.y) : "l"(v)); return r;
}
__device__ __forceinline__ ulonglong2 lds128(unsigned a) {
    ulonglong2 r;
    asm volatile("ld.shared.v2.u64 {%0,%1},[%2];" : "=l"(r.x), "=l"(r.y) : "r"(a));
    return r;
}
__device__ __forceinline__ void sts128(unsigned a, float4 v) {
    asm volatile("st.shared.v4.b32 [%0],{%1,%2,%3,%4};"
                 :: "r"(a), "f"(v.x), "f"(v.y), "f"(v.z), "f"(v.w));
}
__device__ __forceinline__ unsigned smem_u32(const void* p) {
    unsigned a;
    asm("{ .reg .u64 t; cvta.to.shared.u64 t, %1; cvt.u32.u64 %0, t; }"
        : "=r"(a) : "l"(p));
    return a;
}
__device__ __forceinline__ void st_rel(unsigned* p, unsigned v) {
    asm volatile("st.release.gpu.u32 [%0],%1;" :: "l"(p), "r"(v) : "memory");
}
__device__ __forceinline__ unsigned ld_acq(const unsigned* p) {
    unsigned v; asm volatile("ld.acquire.gpu.u32 %0,[%1];" : "=r"(v) : "l"(p) : "memory");
    return v;
}
// prefetch one 1KB W block (256 floats) into smem; one commit group
__device__ __forceinline__ void wpf(unsigned dst, const float* src, int lane) {
    asm volatile("cp.async.cg.shared.global [%0],[%1],16;\n\t"
                 "cp.async.cg.shared.global [%2],[%3],16;\n\t"
                 "cp.async.commit_group;"
                 :: "r"(dst + lane * 16), "l"(src + lane * 4),
                    "r"(dst + 512 + lane * 16), "l"(src + 128 + lane * 4)
                 : "memory");
}
__device__ __forceinline__ void wwait2() {
    asm volatile("cp.async.wait_group 2;" ::: "memory");
}
__device__ __forceinline__ float sig_(float x) { return 1.f / (1.f + __expf(-x)); }
__device__ __forceinline__ float tanh_(float x) {
    float xx = fminf(fmaxf(x, -15.f), 15.f);
    float e = __expf(-2.f * xx);
    return (1.f - e) / (1.f + e);
}

__global__ void init_state() {
    int i = blockIdx.x * blockDim.x + threadIdx.x;
    if (i < Bb * Hh) {
        g_h0[0][i] = 0.f; g_h0[1][i] = 0.f;
        g_h1[0][i] = 0.f; g_h1[1][i] = 0.f;
    }
    if (i < NCTA) g_arrive[i] = 0;
    if (i == 0) g_go = 0;
}

// pack layout: float idx in region = q*64 + i*16 + ct3*4 + k4
// region = ((cta*3+mat)*8+kc)*2+cth, 2048 floats each
__global__ void pack_w(const float* __restrict__ W0, const float* __restrict__ W1,
                       const float* __restrict__ W2)
{
    size_t idx = (size_t)blockIdx.x * blockDim.x + threadIdx.x;
    int k4 = idx & 3, ct3 = (idx >> 2) & 3, i = (idx >> 4) & 3, q = (idx >> 6) & 31;
    int cth = (idx >> 11) & 1, kc = (idx >> 12) & 7;
    int mc = (int)(idx >> 15);
    int mat = mc % 3, cta = mc / 3;
    int c = (cth * 4 + ct3) * 4 + i;
    int gcol = (c >> 3) * Hh + cta * 8 + (c & 7);
    int k = kc * 128 + q * 4 + k4;
    const float* W = (mat == 0) ? W0 : ((mat == 1) ? W1 : W2);
    g_Wpk[idx] = W[(size_t)k * Gg + gcol];
}

// ---------------- GEMM: C = A[M,K]@B[K,N] + bias ----------------------------
__global__ void __launch_bounds__(256) sgemm_bias(
        const float* __restrict__ A, const float* __restrict__ Bm,
        const float* __restrict__ bias, float* __restrict__ C,
        int M, int N, int K)
{
    __shared__ float As[16][128];
    __shared__ float Bs[16][64];
    const int tid = threadIdx.x;
    const int bm = blockIdx.y * 128;
    const int bn = blockIdx.x * 64;
    const int tn = (tid & 15) * 4;
    const int tm = (tid >> 4) * 8;

    u64 acc[4][4];
#pragma unroll
    for (int i = 0; i < 4; ++i)
#pragma unroll
        for (int j = 0; j < 4; ++j) acc[i][j] = 0ULL;

    for (int k0 = 0; k0 < K; k0 += 16) {
#pragma unroll
        for (int i = 0; i < 2; ++i) {
            int fid = tid * 2 + i;
            int r = fid >> 2, kq = fid & 3;
            float4 v = *reinterpret_cast<const float4*>(A + (size_t)(bm + r) * K + k0 + kq * 4);
            As[kq * 4 + 0][r] = v.x;
            As[kq * 4 + 1][r] = v.y;
            As[kq * 4 + 2][r] = v.z;
            As[kq * 4 + 3][r] = v.w;
        }
        {
            int kr = tid >> 4, cq = (tid & 15) * 4;
            *reinterpret_cast<float4*>(&Bs[kr][cq]) =
                *reinterpret_cast<const float4*>(Bm + (size_t)(k0 + kr) * N + bn + cq);
        }
        __syncthreads();
#pragma unroll
        for (int kk = 0; kk < 16; ++kk) {
            ulonglong2 a01 = *reinterpret_cast<const ulonglong2*>(&As[kk][tm]);
            ulonglong2 a23 = *reinterpret_cast<const ulonglong2*>(&As[kk][tm + 4]);
            float4 bv = *reinterpret_cast<const float4*>(&Bs[kk][tn]);
            u64 bs0 = splat2(bv.x), bs1 = splat2(bv.y);
            u64 bs2 = splat2(bv.z), bs3 = splat2(bv.w);
            fma2(acc[0][0], a01.x, bs0); fma2(acc[0][1], a01.x, bs1);
            fma2(acc[0][2], a01.x, bs2); fma2(acc[0][3], a01.x, bs3);
            fma2(acc[1][0], a01.y, bs0); fma2(acc[1][1], a01.y, bs1);
            fma2(acc[1][2], a01.y, bs2); fma2(acc[1][3], a01.y, bs3);
            fma2(acc[2][0], a23.x, bs0); fma2(acc[2][1], a23.x, bs1);
            fma2(acc[2][2], a23.x, bs2); fma2(acc[2][3], a23.x, bs3);
            fma2(acc[3][0], a23.y, bs0); fma2(acc[3][1], a23.y, bs1);
            fma2(acc[3][2], a23.y, bs2); fma2(acc[3][3], a23.y, bs3);
        }
        __syncthreads();
    }

    float4 bb = *reinterpret_cast<const float4*>(bias + bn + tn);
#pragma unroll
    for (int mp = 0; mp < 4; ++mp) {
        float2 p0 = unpack2(acc[mp][0]);
        float2 p1 = unpack2(acc[mp][1]);
        float2 p2 = unpack2(acc[mp][2]);
        float2 p3 = unpack2(acc[mp][3]);
        int row0 = bm + tm + mp * 2;
        float4 o0 = make_float4(p0.x + bb.x, p1.x + bb.y, p2.x + bb.z, p3.x + bb.w);
        float4 o1 = make_float4(p0.y + bb.x, p1.y + bb.y, p2.y + bb.z, p3.y + bb.w);
        *reinterpret_cast<float4*>(C + (size_t)row0 * N + bn + tn) = o0;
        *reinterpret_cast<float4*>(C + (size_t)(row0 + 1) * N + bn + tn) = o1;
    }
}

// ---------------- recurrence pieces ------------------------------------------
__device__ __forceinline__ void stage_h(unsigned hsb, const float* __restrict__ src,
                                        int tid)
{
    const float4* s4 = reinterpret_cast<const float4*>(src);
#pragma unroll
    for (int ii = 0; ii < 16; ++ii) {
        int i4 = tid + ii * 512;
        float4 v = __ldcg(s4 + i4);
        int b = i4 >> 8, q = i4 & 255;
        unsigned off = (unsigned)(b * 4096 + ((q ^ ((b >> 2) & 7)) << 4));
        sts128(hsb + off, v);
    }
}

#define FMA32(w0,w1,w2,w3,h0,h1,h2,h3)                              \
    fma2(a[0][0], w0.x, h0.x); fma2(a[0][0], w0.y, h0.y);           \
    fma2(a[0][1], w0.x, h1.x); fma2(a[0][1], w0.y, h1.y);           \
    fma2(a[0][2], w0.x, h2.x); fma2(a[0][2], w0.y, h2.y);           \
    fma2(a[0][3], w0.x, h3.x); fma2(a[0][3], w0.y, h3.y);           \
    fma2(a[1][0], w1.x, h0.x); fma2(a[1][0], w1.y, h0.y);           \
    fma2(a[1][1], w1.x, h1.x); fma2(a[1][1], w1.y, h1.y);           \
    fma2(a[1][2], w1.x, h2.x); fma2(a[1][2], w1.y, h2.y);           \
    fma2(a[1][3], w1.x, h3.x); fma2(a[1][3], w1.y, h3.y);           \
    fma2(a[2][0], w2.x, h0.x); fma2(a[2][0], w2.y, h0.y);           \
    fma2(a[2][1], w2.x, h1.x); fma2(a[2][1], w2.y, h1.y);           \
    fma2(a[2][2], w2.x, h2.x); fma2(a[2][2], w2.y, h2.y);           \
    fma2(a[2][3], w2.x, h3.x); fma2(a[2][3], w2.y, h3.y);           \
    fma2(a[3][0], w3.x, h0.x); fma2(a[3][0], w3.y, h0.y);           \
    fma2(a[3][1], w3.x, h1.x); fma2(a[3][1], w3.y, h1.y);           \
    fma2(a[3][2], w3.x, h2.x); fma2(a[3][2], w3.y, h2.y);           \
    fma2(a[3][3], w3.x, h3.x); fma2(a[3][3], w3.y, h3.y)

// 4 q-iters from one 1KB W slot; software-pipelined (preload q+1 during q FMAs)
__device__ __forceinline__ void mma4(u64 (&a)[4][4], unsigned wslot, unsigned hrow,
                                     int qh0, int q0, int bt, int ct3)
{
    unsigned wq = wslot + (unsigned)(ct3 * 16);
    ulonglong2 w0 = lds128(wq), w1 = lds128(wq + 64),
               w2 = lds128(wq + 128), w3 = lds128(wq + 192);
    unsigned off = hrow + (unsigned)((qh0 + (q0 ^ bt)) << 4);
    ulonglong2 h0 = lds128(off), h1 = lds128(off + 4096),
               h2 = lds128(off + 8192), h3 = lds128(off + 12288);
#pragma unroll
    for (int qin = 0; qin < 4; ++qin) {
        ulonglong2 nw0, nw1, nw2, nw3, nh0, nh1, nh2, nh3;
        if (qin < 3) {
            unsigned wq2 = wslot + (unsigned)((qin + 1) * 256 + ct3 * 16);
            nw0 = lds128(wq2);       nw1 = lds128(wq2 + 64);
            nw2 = lds128(wq2 + 128); nw3 = lds128(wq2 + 192);
            unsigned off2 = hrow + (unsigned)((qh0 + ((q0 + qin + 1) ^ bt)) << 4);
            nh0 = lds128(off2);        nh1 = lds128(off2 + 4096);
            nh2 = lds128(off2 + 8192); nh3 = lds128(off2 + 12288);
        }
        FMA32(w0, w1, w2, w3, h0, h1, h2, h3);
        if (qin < 3) {
            w0 = nw0; w1 = nw1; w2 = nw2; w3 = nw3;
            h0 = nh0; h1 = nh1; h2 = nh2; h3 = nh3;
        }
    }
}

// one matrix = 8 blocks; prefetch block n+2 BEFORE computing n (depth-2 in flight)
__device__ __forceinline__ void run_mat(u64 (&acc)[4][4], bool active, int &cb,
    unsigned wring, const float* __restrict__ wg, unsigned hrow,
    int qh0, int bt, int ct3, int lane)
{
#pragma unroll 1
    for (int blk = 0; blk < 8; ++blk) {
        int pb = cb + 2; if (pb >= 24) pb -= 24;
        wpf(wring + (unsigned)((pb % 3) * 1024),
            wg + (size_t)(pb >> 3) * 32768 + (pb & 7) * 256, lane);
        wwait2();
        __syncwarp();
        if (active)
            mma4(acc, wring + (unsigned)((cb % 3) * 1024), hrow, qh0, blk * 4, bt, ct3);
        ++cb; if (cb >= 24) cb = 0;
    }
}

// red stride: c rows padded to 36 words (conflict-free gate reads)
__device__ __forceinline__ void store_red(float* red, u64 (&acc)[4][4],
                                          int kc, int c0i, int b0)
{
#pragma unroll
    for (int i = 0; i < 4; ++i) {
        float2 p0 = unpack2(acc[i][0]);
        float2 p1 = unpack2(acc[i][1]);
        float2 p2 = unpack2(acc[i][2]);
        float2 p3 = unpack2(acc[i][3]);
        float4 v = make_float4(p0.x + p0.y, p1.x + p1.y, p2.x + p2.y, p3.x + p3.y);
        *reinterpret_cast<float4*>(&red[kc * 1152 + (c0i + i) * 36 + b0]) = v;
    }
}

__device__ __forceinline__ void grid_bar(unsigned target) {
    __syncthreads();
    const unsigned tid = threadIdx.x;
    if (tid == 0) { __threadfence(); st_rel(&g_arrive[blockIdx.x], target); }
    if (blockIdx.x == 0) {
        if (tid < NCTA) { while (ld_acq(&g_arrive[tid]) < target) {} }
        __syncthreads();
        if (tid == 0) st_rel(&g_go, target);
    }
    if (tid == 0) { while (ld_acq(&g_go) < target) {} }
    __syncthreads();
}

// ---------------- persistent 2-layer LSTM recurrence -------------------------
__global__ void __launch_bounds__(512, 1) lstm_rec4(const float* __restrict__ b1)
{
    extern __shared__ float smem[];
    float* red = smem + 32768;                       // 36KB after 128KB hs
    const unsigned hsb = smem_u32(smem);

    const int tid = threadIdx.x;
    const int lane = tid & 31;
    const int wid = tid >> 5;
    const int kc = tid >> 6;
    const int cth = (tid >> 5) & 1;
    const int ct3 = lane >> 3;
    const int bt = lane & 7;
    const int c0i = (cth * 4 + ct3) * 4;
    const int b0 = bt * 4;
    const int cta = blockIdx.x;
    const int jbase = cta * 8;
    const int qh0 = kc * 32;
    const unsigned hrow = hsb + (unsigned)(b0 * 4096);
    const unsigned wring = hsb + 167936u + (unsigned)(wid * 3072);
    const float* wg = g_Wpk + ((((size_t)cta * 3 + 0) * 8 + kc) * 2 + cth) * 2048;

    const int gb = tid >> 3;
    const int gj = tid & 7;
    float c0s = 0.f, c1s = 0.f;
    float bias1[4];
    if (tid < 256) {
#pragma unroll
        for (int g = 0; g < 4; ++g) bias1[g] = b1[g * Hh + jbase + gj];
    }

    // warm up W stream: blocks 0,1 -> slots 0,1
    int cb = 0;
    wpf(wring, wg, lane);
    wpf(wring + 1024, wg + 256, lane);

    for (int s = 0; s <= Tt; ++s) {
        const int rb = (s + 1) & 1;
        const int wb = s & 1;

        stage_h(hsb, g_h0[rb], tid);
        __syncthreads();

        float xw[4];
        if (tid < 256 && s < Tt) {
#pragma unroll
            for (int g = 0; g < 4; ++g)
                xw[g] = __ldcg(&g_XW[((size_t)gb * Tt + s) * Gg + g * Hh + jbase + gj]);
        }

        u64 acc[4][4];
#pragma unroll
        for (int i = 0; i < 4; ++i)
#pragma unroll
            for (int j = 0; j < 4; ++j) acc[i][j] = 0ULL;
        run_mat(acc, s < Tt, cb, wring, wg, hrow, qh0, bt, ct3, lane);  // Wh0 x h0
        if (s < Tt) store_red(red, acc, kc, c0i, b0);
        __syncthreads();

        float z0[4];
        if (tid < 256 && s < Tt) {
#pragma unroll
            for (int g = 0; g < 4; ++g) {
                float t = xw[g];
#pragma unroll
                for (int kk = 0; kk < 8; ++kk)
                    t += red[kk * 1152 + (g * 8 + gj) * 36 + gb];
                z0[g] = t;
            }
        }
        __syncthreads();

        u64 accB[4][4];
#pragma unroll
        for (int i = 0; i < 4; ++i)
#pragma unroll
            for (int j = 0; j < 4; ++j) accB[i][j] = 0ULL;
        run_mat(accB, s > 0, cb, wring, wg, hrow, qh0, bt, ct3, lane);  // Wx1 x h0
        __syncthreads();

        stage_h(hsb, g_h1[rb], tid);                                   // hs := h1(s-2)
        __syncthreads();

        run_mat(accB, s > 0, cb, wring, wg, hrow, qh0, bt, ct3, lane);  // + Wh1 x h1
        if (s > 0) store_red(red, accB, kc, c0i, b0);
        __syncthreads();

        if (tid < 256) {
            if (s < Tt) {
                float ci = sig_(z0[0]), cf = sig_(z0[1]);
                float cg = tanh_(z0[2]), co = sig_(z0[3]);
                c0s = cf * c0s + ci * cg;
                g_h0[wb][gb * Hh + jbase + gj] = co * tanh_(c0s);
            }
            if (s > 0) {
                float z1[4];
#pragma unroll
                for (int g = 0; g < 4; ++g) {
                    float t = bias1[g];
#pragma unroll
                    for (int kk = 0; kk < 8; ++kk)
                        t += red[kk * 1152 + (g * 8 + gj) * 36 + gb];
                    z1[g] = t;
                }
                float ci = sig_(z1[0]), cf = sig_(z1[1]);
                float cg = tanh_(z1[2]), co = sig_(z1[3]);
                c1s = cf * c1s + ci * cg;
                float hn = co * tanh_(c1s);
                g_h1[wb][gb * Hh + jbase + gj] = hn;
                g_Y[((size_t)gb * Tt + (s - 1)) * Hh + jbase + gj] = hn;
            }
        }
        grid_bar((unsigned)(s + 1));
    }
    asm volatile("cp.async.wait_group 0;" ::: "memory");
}

// ---------------- launch ------------------------------------------------------
extern "C" void kernel_launch(void* const* d_in, const int* in_sizes, int n_in,
                              void* d_out, int out_size)
{
    const float* x   = (const float*)d_in[0];
    const float* Wx0 = (const float*)d_in[1];
    const float* Wh0 = (const float*)d_in[2];
    const float* b0v = (const float*)d_in[3];
    const float* Wx1 = (const float*)d_in[4];
    const float* Wh1 = (const float*)d_in[5];
    const float* b1v = (const float*)d_in[6];
    const float* Wd  = (const float*)d_in[7];
    const float* bdv = (const float*)d_in[8];
    float* out = (float*)d_out;

    float* xw; cudaGetSymbolAddress((void**)&xw, g_XW);
    float* yv; cudaGetSymbolAddress((void**)&yv, g_Y);

    cudaFuncSetAttribute(lstm_rec4,
                         cudaFuncAttributeMaxDynamicSharedMemorySize, SMEMB);

    init_state<<<64, 512>>>();
    pack_w<<<PKTOT / 256, 256>>>(Wh0, Wx1, Wh1);

    sgemm_bias<<<dim3(Gg / 64, (Bb * Tt) / 128), 256>>>(x, Wx0, b0v, xw,
                                                        Bb * Tt, Gg, Dd);
    lstm_rec4<<<NCTA, 512, SMEMB>>>(b1v);

    sgemm_bias<<<dim3(Oo / 64, (Bb * Tt) / 128), 256>>>(yv, Wd, bdv, out,
                                                        Bb * Tt, Oo, Hh);
}

// round 12
// speedup vs baseline: 6.7194x; 1.7895x over previous
#include <cuda_runtime.h>
#include <cuda_bf16.h>
#include <cstdint>

typedef unsigned long long u64;

#define Bb 32
#define Tt 512
#define Dd 512
#define Hh 1024
#define Gg 4096
#define Oo 512
#define NCTA 128
#define SMT 217088

__device__ float g_XW[(size_t)Bb * Tt * Gg];
__device__ float g_Y [(size_t)Bb * Tt * Hh];
__device__ char  g_Wf[(size_t)128 * 3 * 8 * 2 * 8 * 1024];  // 48MB A-frag images
__device__ char  g_Bf[2][2][2][65536];                      // [layer][buf][hi/lo]
__device__ unsigned g_arrive[NCTA];
__device__ unsigned g_go;

// ---------------- helpers ----------------------------------------------------
__device__ __forceinline__ void fma2(u64 &d, u64 a, u64 b) {
    asm volatile("fma.rn.f32x2 %0, %1, %2, %0;" : "+l"(d) : "l"(a), "l"(b));
}
__device__ __forceinline__ u64 splat2(float x) {
    u64 r; asm("mov.b64 %0, {%1, %1};" : "=l"(r) : "f"(x)); return r;
}
__device__ __forceinline__ float2 unpack2(u64 v) {
    float2 r; asm("mov.b64 {%0, %1}, %2;" : "=f"(r.x), "=f"(r.y) : "l"(v)); return r;
}
__device__ __forceinline__ unsigned smem_u32(const void* p) {
    unsigned a;
    asm("{ .reg .u64 t; cvta.to.shared.u64 t, %1; cvt.u32.u64 %0, t; }"
        : "=r"(a) : "l"(p));
    return a;
}
__device__ __forceinline__ void st_rel(unsigned* p, unsigned v) {
    asm volatile("st.release.gpu.u32 [%0],%1;" :: "l"(p), "r"(v) : "memory");
}
__device__ __forceinline__ unsigned ld_acq(const unsigned* p) {
    unsigned v; asm volatile("ld.acquire.gpu.u32 %0,[%1];" : "=r"(v) : "l"(p) : "memory");
    return v;
}
__device__ __forceinline__ void cp16(unsigned d, const char* s) {
    asm volatile("cp.async.cg.shared.global [%0],[%1],16;" :: "r"(d), "l"(s) : "memory");
}
#define CPC  asm volatile("cp.async.commit_group;" ::: "memory")
#define CPW0 asm volatile("cp.async.wait_group 0;" ::: "memory")
#define CPW2 asm volatile("cp.async.wait_group 2;" ::: "memory")
// prefetch one 1KB packed-W block; one commit group
__device__ __forceinline__ void wpf(unsigned dst, const char* src, int lane) {
    asm volatile("cp.async.cg.shared.global [%0],[%1],16;\n\t"
                 "cp.async.cg.shared.global [%2],[%3],16;\n\t"
                 "cp.async.commit_group;"
                 :: "r"(dst + lane * 16), "l"(src + lane * 16),
                    "r"(dst + 512 + lane * 16), "l"(src + 512 + lane * 16)
                 : "memory");
}
__device__ __forceinline__ void mmabf(float* d, const unsigned* a, unsigned b0, unsigned b1) {
    asm volatile("mma.sync.aligned.m16n8k16.row.col.f32.bf16.bf16.f32 "
                 "{%0,%1,%2,%3},{%4,%5,%6,%7},{%8,%9},{%0,%1,%2,%3};"
                 : "+f"(d[0]), "+f"(d[1]), "+f"(d[2]), "+f"(d[3])
                 : "r"(a[0]), "r"(a[1]), "r"(a[2]), "r"(a[3]), "r"(b0), "r"(b1));
}
__device__ __forceinline__ float sig_(float x) { return 1.f / (1.f + __expf(-x)); }
__device__ __forceinline__ float tanh_(float x) {
    float xx = fminf(fmaxf(x, -15.f), 15.f);
    float e = __expf(-2.f * xx);
    return (1.f - e) / (1.f + e);
}

__global__ void init_state() {
    int i = blockIdx.x * blockDim.x + threadIdx.x;
    uint4* bf = reinterpret_cast<uint4*>(&g_Bf[0][0][0][0]);
    if (i < 32768) bf[i] = make_uint4(0, 0, 0, 0);   // 512KB zeros
    if (i < NCTA) g_arrive[i] = 0;
    if (i == 0) g_go = 0;
}

// ---------------- pack: W -> A-fragment hi/lo images -------------------------
// block(1KB) = [lane(32)][hi 16B | lo 16B]; region idx = ((cta*3+mat)*8+kc)*2+mh
__global__ void pack_hmma(const float* __restrict__ W0, const float* __restrict__ W1,
                          const float* __restrict__ W2)
{
    unsigned id = blockIdx.x * blockDim.x + threadIdx.x;  // 6291456 total
    int reg = id & 3, lane = (id >> 2) & 31, tile = (id >> 7) & 7;
    int mh = (id >> 10) & 1, kc = (id >> 11) & 7;
    unsigned rm = id >> 14;
    int mat = rm % 3, cta = (int)(rm / 3);
    int r = lane >> 2, cq = (lane & 3) * 2;
    int m = mh * 16 + r + (reg & 1) * 8;                  // D-row 0..31
    int k = kc * 128 + tile * 16 + cq + ((reg >> 1) & 1) * 8;
    int col = (m >> 3) * Hh + cta * 8 + (m & 7);          // gate-major column
    const float* W = (mat == 0) ? W0 : ((mat == 1) ? W1 : W2);
    float w0 = W[(size_t)k * Gg + col];
    float w1 = W[(size_t)(k + 1) * Gg + col];
    __nv_bfloat16 h0 = __float2bfloat16(w0), h1 = __float2bfloat16(w1);
    __nv_bfloat16 l0 = __float2bfloat16(w0 - __bfloat162float(h0));
    __nv_bfloat16 l1 = __float2bfloat16(w1 - __bfloat162float(h1));
    size_t base = (size_t)((((cta * 3 + mat) * 8 + kc) * 2 + mh) * 8 + tile) * 1024
                  + (size_t)(lane * 32);
    unsigned hp = (unsigned)*(unsigned short*)&h0 | ((unsigned)*(unsigned short*)&h1 << 16);
    unsigned lp = (unsigned)*(unsigned short*)&l0 | ((unsigned)*(unsigned short*)&l1 << 16);
    *(unsigned*)(g_Wf + base + reg * 4) = hp;
    *(unsigned*)(g_Wf + base + 16 + reg * 4) = lp;
}

// ---------------- GEMM: C = A[M,K]@B[K,N] + bias (proven) --------------------
__global__ void __launch_bounds__(256) sgemm_bias(
        const float* __restrict__ A, const float* __restrict__ Bm,
        const float* __restrict__ bias, float* __restrict__ C,
        int M, int N, int K)
{
    __shared__ float As[16][128];
    __shared__ float Bs[16][64];
    const int tid = threadIdx.x;
    const int bm = blockIdx.y * 128;
    const int bn = blockIdx.x * 64;
    const int tn = (tid & 15) * 4;
    const int tm = (tid >> 4) * 8;

    u64 acc[4][4];
#pragma unroll
    for (int i = 0; i < 4; ++i)
#pragma unroll
        for (int j = 0; j < 4; ++j) acc[i][j] = 0ULL;

    for (int k0 = 0; k0 < K; k0 += 16) {
#pragma unroll
        for (int i = 0; i < 2; ++i) {
            int fid = tid * 2 + i;
            int r = fid >> 2, kq = fid & 3;
            float4 v = *reinterpret_cast<const float4*>(A + (size_t)(bm + r) * K + k0 + kq * 4);
            As[kq * 4 + 0][r] = v.x;
            As[kq * 4 + 1][r] = v.y;
            As[kq * 4 + 2][r] = v.z;
            As[kq * 4 + 3][r] = v.w;
        }
        {
            int kr = tid >> 4, cq = (tid & 15) * 4;
            *reinterpret_cast<float4*>(&Bs[kr][cq]) =
                *reinterpret_cast<const float4*>(Bm + (size_t)(k0 + kr) * N + bn + cq);
        }
        __syncthreads();
#pragma unroll
        for (int kk = 0; kk < 16; ++kk) {
            ulonglong2 a01 = *reinterpret_cast<const ulonglong2*>(&As[kk][tm]);
            ulonglong2 a23 = *reinterpret_cast<const ulonglong2*>(&As[kk][tm + 4]);
            float4 bv = *reinterpret_cast<const float4*>(&Bs[kk][tn]);
            u64 bs0 = splat2(bv.x), bs1 = splat2(bv.y);
            u64 bs2 = splat2(bv.z), bs3 = splat2(bv.w);
            fma2(acc[0][0], a01.x, bs0); fma2(acc[0][1], a01.x, bs1);
            fma2(acc[0][2], a01.x, bs2); fma2(acc[0][3], a01.x, bs3);
            fma2(acc[1][0], a01.y, bs0); fma2(acc[1][1], a01.y, bs1);
            fma2(acc[1][2], a01.y, bs2); fma2(acc[1][3], a01.y, bs3);
            fma2(acc[2][0], a23.x, bs0); fma2(acc[2][1], a23.x, bs1);
            fma2(acc[2][2], a23.x, bs2); fma2(acc[2][3], a23.x, bs3);
            fma2(acc[3][0], a23.y, bs0); fma2(acc[3][1], a23.y, bs1);
            fma2(acc[3][2], a23.y, bs2); fma2(acc[3][3], a23.y, bs3);
        }
        __syncthreads();
    }

    float4 bb = *reinterpret_cast<const float4*>(bias + bn + tn);
#pragma unroll
    for (int mp = 0; mp < 4; ++mp) {
        float2 p0 = unpack2(acc[mp][0]);
        float2 p1 = unpack2(acc[mp][1]);
        float2 p2 = unpack2(acc[mp][2]);
        float2 p3 = unpack2(acc[mp][3]);
        int row0 = bm + tm + mp * 2;
        float4 o0 = make_float4(p0.x + bb.x, p1.x + bb.y, p2.x + bb.z, p3.x + bb.w);
        float4 o1 = make_float4(p0.y + bb.x, p1.y + bb.y, p2.y + bb.z, p3.y + bb.w);
        *reinterpret_cast<float4*>(C + (size_t)row0 * N + bn + tn) = o0;
        *reinterpret_cast<float4*>(C + (size_t)(row0 + 1) * N + bn + tn) = o1;
    }
}

__device__ __forceinline__ void grid_bar(unsigned target) {
    __syncthreads();
    const unsigned tid = threadIdx.x;
    if (tid == 0) { __threadfence(); st_rel(&g_arrive[blockIdx.x], target); }
    if (blockIdx.x == 0) {
        if (tid < NCTA) { while (ld_acq(&g_arrive[tid]) < target) {} }
        __syncthreads();
        if (tid == 0) st_rel(&g_go, target);
    }
    if (tid == 0) { while (ld_acq(&g_go) < target) {} }
    __syncthreads();
}

// ---------------- recurrence pieces ------------------------------------------
// stage B-fragment buffers (h hi/lo, 64KB each) into smem [0,64K) + [64K,128K)
__device__ __forceinline__ void stage_B(unsigned sb, const char* hi, const char* lo,
                                        int tid)
{
#pragma unroll
    for (int p = 0; p < 8; ++p) {
        unsigned o = (unsigned)((p * 512 + tid) * 16);
        cp16(sb + o, hi + o);
        cp16(sb + 65536 + o, lo + o);
    }
    CPC;
}

// one matrix = 8 k-tiles; 3-term bf16-split HMMA, W via 3-slot cp.async ring
__device__ __forceinline__ void run_mat8(float (&acc)[4][4], bool active, int &cb,
    unsigned wring, const char* __restrict__ wg, unsigned sb, int kc, int lane)
{
#pragma unroll 1
    for (int tile = 0; tile < 8; ++tile) {
        int pb = cb + 2; if (pb >= 24) pb -= 24;
        wpf(wring + (unsigned)((pb % 3) * 1024),
            wg + (size_t)(pb >> 3) * 131072 + (size_t)(pb & 7) * 1024, lane);
        CPW2;
        __syncwarp();
        if (active) {
            unsigned sa = wring + (unsigned)((cb % 3) * 1024 + lane * 32);
            unsigned ah[4], al[4];
            asm volatile("ld.shared.v4.b32 {%0,%1,%2,%3},[%4];"
                : "=r"(ah[0]), "=r"(ah[1]), "=r"(ah[2]), "=r"(ah[3]) : "r"(sa));
            asm volatile("ld.shared.v4.b32 {%0,%1,%2,%3},[%4];"
                : "=r"(al[0]), "=r"(al[1]), "=r"(al[2]), "=r"(al[3]) : "r"(sa + 16));
            int kt = kc * 8 + tile;
#pragma unroll
            for (int n8 = 0; n8 < 4; ++n8) {
                unsigned bo = sb + (unsigned)(((kt * 4 + n8) * 32 + lane) * 8);
                unsigned bh0, bh1, bl0, bl1;
                asm volatile("ld.shared.v2.b32 {%0,%1},[%2];"
                             : "=r"(bh0), "=r"(bh1) : "r"(bo));
                asm volatile("ld.shared.v2.b32 {%0,%1},[%2];"
                             : "=r"(bl0), "=r"(bl1) : "r"(bo + 65536));
                mmabf(acc[n8], ah, bh0, bh1);   // hi*hi
                mmabf(acc[n8], al, bh0, bh1);   // lo*hi
                mmabf(acc[n8], ah, bl0, bl1);   // hi*lo
            }
        }
        ++cb; if (cb >= 24) cb = 0;
    }
}

__device__ __forceinline__ void store_redH(float* red, float (&acc)[4][4],
                                           int kc, int mh, int lane)
{
    int r = lane >> 2, cq = (lane & 3) * 2;
#pragma unroll
    for (int n8 = 0; n8 < 4; ++n8) {
        int b = n8 * 8 + cq;
        int c = mh * 16 + r;
        *reinterpret_cast<float2*>(&red[kc * 1152 + c * 36 + b]) =
            make_float2(acc[n8][0], acc[n8][1]);
        *reinterpret_cast<float2*>(&red[kc * 1152 + (c + 8) * 36 + b]) =
            make_float2(acc[n8][2], acc[n8][3]);
    }
}

// write h value into B-fragment global buffers (hi + lo), 2B each
__device__ __forceinline__ void wr_frag(char* bhi, char* blo, int k, int b, float h) {
    int kt = k >> 4, kin = k & 15;
    int reg = kin >> 3, quad = (kin >> 1) & 3, half = kin & 1;
    unsigned off = (unsigned)((((kt * 4 + (b >> 3)) * 32) + (b & 7) * 4 + quad) * 8
                              + reg * 4 + half * 2);
    __nv_bfloat16 hh = __float2bfloat16(h);
    __nv_bfloat16 hl = __float2bfloat16(h - __bfloat162float(hh));
    *(__nv_bfloat16*)(bhi + off) = hh;
    *(__nv_bfloat16*)(blo + off) = hl;
}

// ---------------- persistent 2-layer LSTM recurrence (HMMA) ------------------
// SMEM: [0,64K) Bhi  [64K,128K) Blo  [128K,176K) W ring 16x3KB  [176K..) red 36KB
__global__ void __launch_bounds__(512, 1) lstm_hm(const float* __restrict__ b1v)
{
    extern __shared__ char smc[];
    float* red = reinterpret_cast<float*>(smc + 180224);
    const unsigned sb = smem_u32(smc);

    const int tid = threadIdx.x, lane = tid & 31, wid = tid >> 5;
    const int kc = wid >> 1, mh = wid & 1;
    const int cta = blockIdx.x, jbase = cta * 8;
    const unsigned wring = sb + 131072u + (unsigned)(wid * 3072);
    const char* wg = g_Wf + (size_t)(((cta * 3) * 8 + kc) * 2 + mh) * 8192;

    const int gb = tid >> 3, gj = tid & 7;
    float c0s = 0.f, c1s = 0.f;
    float bias1[4];
    if (tid < 256) {
#pragma unroll
        for (int g = 0; g < 4; ++g) bias1[g] = b1v[g * Hh + jbase + gj];
    }

    int cb = 0;
    wpf(wring, wg, lane);
    wpf(wring + 1024, wg + 1024, lane);

    for (int s = 0; s <= Tt; ++s) {
        const int rb = (s + 1) & 1;
        const int wb = s & 1;

        stage_B(sb, g_Bf[0][rb][0], g_Bf[0][rb][1], tid);   // h0(s-1) frags
        CPW0;
        __syncthreads();

        float xw[4];
        if (tid < 256 && s < Tt) {
#pragma unroll
            for (int g = 0; g < 4; ++g)
                xw[g] = __ldcg(&g_XW[((size_t)gb * Tt + s) * Gg + g * Hh + jbase + gj]);
        }

        float acc[4][4];
#pragma unroll
        for (int i = 0; i < 4; ++i)
#pragma unroll
            for (int j = 0; j < 4; ++j) acc[i][j] = 0.f;
        run_mat8(acc, s < Tt, cb, wring, wg, sb, kc, lane);   // Wh0 x h0
        if (s < Tt) store_redH(red, acc, kc, mh, lane);
        __syncthreads();

        float z0[4];
        if (tid < 256 && s < Tt) {
#pragma unroll
            for (int g = 0; g < 4; ++g) {
                float t = xw[g];
#pragma unroll
                for (int kk = 0; kk < 8; ++kk)
                    t += red[kk * 1152 + (g * 8 + gj) * 36 + gb];
                z0[g] = t;
            }
        }
        __syncthreads();

        float accB[4][4];
#pragma unroll
        for (int i = 0; i < 4; ++i)
#pragma unroll
            for (int j = 0; j < 4; ++j) accB[i][j] = 0.f;
        run_mat8(accB, s > 0, cb, wring, wg, sb, kc, lane);   // Wx1 x h0
        __syncthreads();                                      // done reading h0

        stage_B(sb, g_Bf[1][rb][0], g_Bf[1][rb][1], tid);     // h1(s-2) frags
        CPW0;
        __syncthreads();

        run_mat8(accB, s > 0, cb, wring, wg, sb, kc, lane);   // + Wh1 x h1
        if (s > 0) store_redH(red, accB, kc, mh, lane);
        __syncthreads();

        if (tid < 256) {
            if (s < Tt) {
                float I = sig_(z0[0]), F = sig_(z0[1]);
                float G = tanh_(z0[2]), O = sig_(z0[3]);
                c0s = F * c0s + I * G;
                float h = O * tanh_(c0s);
                wr_frag(g_Bf[0][wb][0], g_Bf[0][wb][1], jbase + gj, gb, h);
            }
            if (s > 0) {
                float z1[4];
#pragma unroll
                for (int g = 0; g < 4; ++g) {
                    float t = bias1[g];
#pragma unroll
                    for (int kk = 0; kk < 8; ++kk)
                        t += red[kk * 1152 + (g * 8 + gj) * 36 + gb];
                    z1[g] = t;
                }
                float I = sig_(z1[0]), F = sig_(z1[1]);
                float G = tanh_(z1[2]), O = sig_(z1[3]);
                c1s = F * c1s + I * G;
                float h = O * tanh_(c1s);
                wr_frag(g_Bf[1][wb][0], g_Bf[1][wb][1], jbase + gj, gb, h);
                g_Y[((size_t)gb * Tt + (s - 1)) * Hh + jbase + gj] = h;
            }
        }
        grid_bar((unsigned)(s + 1));
    }
    CPW0;
}

// ---------------- launch ------------------------------------------------------
extern "C" void kernel_launch(void* const* d_in, const int* in_sizes, int n_in,
                              void* d_out, int out_size)
{
    const float* x   = (const float*)d_in[0];
    const float* Wx0 = (const float*)d_in[1];
    const float* Wh0 = (const float*)d_in[2];
    const float* b0v = (const float*)d_in[3];
    const float* Wx1 = (const float*)d_in[4];
    const float* Wh1 = (const float*)d_in[5];
    const float* b1v = (const float*)d_in[6];
    const float* Wd  = (const float*)d_in[7];
    const float* bdv = (const float*)d_in[8];
    float* out = (float*)d_out;

    float* xw; cudaGetSymbolAddress((void**)&xw, g_XW);
    float* yv; cudaGetSymbolAddress((void**)&yv, g_Y);

    cudaFuncSetAttribute(lstm_hm, cudaFuncAttributeMaxDynamicSharedMemorySize, SMT);

    init_state<<<64, 512>>>();
    pack_hmma<<<24576, 256>>>(Wh0, Wx1, Wh1);

    sgemm_bias<<<dim3(Gg / 64, (Bb * Tt) / 128), 256>>>(x, Wx0, b0v, xw,
                                                        Bb * Tt, Gg, Dd);
    lstm_hm<<<NCTA, 512, SMT>>>(b1v);

    sgemm_bias<<<dim3(Oo / 64, (Bb * Tt) / 128), 256>>>(yv, Wd, bdv, out,
                                                        Bb * Tt, Oo, Hh);
}

// round 13
// speedup vs baseline: 7.4835x; 1.1137x over previous
#include <cuda_runtime.h>
#include <cuda_bf16.h>
#include <cstdint>

typedef unsigned long long u64;

#define Bb 32
#define Tt 512
#define Dd 512
#define Hh 1024
#define Gg 4096
#define Oo 512
#define NCTA 128
#define SMT 217088

__device__ float g_XW[(size_t)Bb * Tt * Gg];
__device__ float g_Y [(size_t)Bb * Tt * Hh];
__device__ char  g_Wf[(size_t)128 * 16 * 24576];   // 48MB A-frag images (24 blk/region)
__device__ char  g_Bf[2][2][131072];               // [layer][buf] interleaved hi|lo
__device__ unsigned g_arrive[NCTA];
__device__ unsigned g_go;

// ---------------- helpers ----------------------------------------------------
__device__ __forceinline__ void fma2(u64 &d, u64 a, u64 b) {
    asm volatile("fma.rn.f32x2 %0, %1, %2, %0;" : "+l"(d) : "l"(a), "l"(b));
}
__device__ __forceinline__ u64 splat2(float x) {
    u64 r; asm("mov.b64 %0, {%1, %1};" : "=l"(r) : "f"(x)); return r;
}
__device__ __forceinline__ float2 unpack2(u64 v) {
    float2 r; asm("mov.b64 {%0, %1}, %2;" : "=f"(r.x), "=f"(r.y) : "l"(v)); return r;
}
__device__ __forceinline__ unsigned smem_u32(const void* p) {
    unsigned a;
    asm("{ .reg .u64 t; cvta.to.shared.u64 t, %1; cvt.u32.u64 %0, t; }"
        : "=r"(a) : "l"(p));
    return a;
}
__device__ __forceinline__ void st_rel(unsigned* p, unsigned v) {
    asm volatile("st.release.gpu.u32 [%0],%1;" :: "l"(p), "r"(v) : "memory");
}
__device__ __forceinline__ unsigned ld_acq(const unsigned* p) {
    unsigned v; asm volatile("ld.acquire.gpu.u32 %0,[%1];" : "=r"(v) : "l"(p) : "memory");
    return v;
}
__device__ __forceinline__ void cp16(unsigned d, const char* s) {
    asm volatile("cp.async.cg.shared.global [%0],[%1],16;" :: "r"(d), "l"(s) : "memory");
}
#define CPC  asm volatile("cp.async.commit_group;" ::: "memory")
#define CPW0 asm volatile("cp.async.wait_group 0;" ::: "memory")
#define CPW1 asm volatile("cp.async.wait_group 1;" ::: "memory")
#define CPW2 asm volatile("cp.async.wait_group 2;" ::: "memory")
__device__ __forceinline__ void wpf(unsigned dst, const char* src, int lane) {
    asm volatile("cp.async.cg.shared.global [%0],[%1],16;\n\t"
                 "cp.async.cg.shared.global [%2],[%3],16;\n\t"
                 "cp.async.commit_group;"
                 :: "r"(dst + lane * 16), "l"(src + lane * 16),
                    "r"(dst + 512 + lane * 16), "l"(src + 512 + lane * 16)
                 : "memory");
}
__device__ __forceinline__ void mmabf(float* d, const unsigned* a, unsigned b0, unsigned b1) {
    asm volatile("mma.sync.aligned.m16n8k16.row.col.f32.bf16.bf16.f32 "
                 "{%0,%1,%2,%3},{%4,%5,%6,%7},{%8,%9},{%0,%1,%2,%3};"
                 : "+f"(d[0]), "+f"(d[1]), "+f"(d[2]), "+f"(d[3])
                 : "r"(a[0]), "r"(a[1]), "r"(a[2]), "r"(a[3]), "r"(b0), "r"(b1));
}
__device__ __forceinline__ void ldsA(unsigned sa, unsigned* ah, unsigned* al) {
    asm volatile("ld.shared.v4.b32 {%0,%1,%2,%3},[%4];"
        : "=r"(ah[0]), "=r"(ah[1]), "=r"(ah[2]), "=r"(ah[3]) : "r"(sa));
    asm volatile("ld.shared.v4.b32 {%0,%1,%2,%3},[%4];"
        : "=r"(al[0]), "=r"(al[1]), "=r"(al[2]), "=r"(al[3]) : "r"(sa + 16));
}
__device__ __forceinline__ float sig_(float x) { return 1.f / (1.f + __expf(-x)); }
__device__ __forceinline__ float tanh_(float x) {
    float xx = fminf(fmaxf(x, -15.f), 15.f);
    float e = __expf(-2.f * xx);
    return (1.f - e) / (1.f + e);
}

__global__ void init_state() {
    int i = blockIdx.x * blockDim.x + threadIdx.x;
    uint4* bf = reinterpret_cast<uint4*>(&g_Bf[0][0][0]);
    if (i < 32768) bf[i] = make_uint4(0, 0, 0, 0);
    if (i < NCTA) g_arrive[i] = 0;
    if (i == 0) g_go = 0;
}

// ---------------- pack: W -> A-frag images, consumption-order blocks ---------
// region (cta,kc,mh) = 24 x 1KB blocks: [m0t0|m1t0|m0t1|m1t1|...|m0t7|m1t7|m2t0..m2t7]
__global__ void pack_hmma(const float* __restrict__ W0, const float* __restrict__ W1,
                          const float* __restrict__ W2)
{
    unsigned id = blockIdx.x * blockDim.x + threadIdx.x;   // 6291456 total
    int reg = id & 3, lane = (id >> 2) & 31, tile = (id >> 7) & 7;
    int mh = (id >> 10) & 1, kc = (id >> 11) & 7;
    unsigned rm = id >> 14;
    int mat = rm % 3, cta = (int)(rm / 3);
    int r = lane >> 2, cq = (lane & 3) * 2;
    int m = mh * 16 + r + (reg & 1) * 8;
    int k = kc * 128 + tile * 16 + cq + ((reg >> 1) & 1) * 8;
    int col = (m >> 3) * Hh + cta * 8 + (m & 7);
    const float* W = (mat == 0) ? W0 : ((mat == 1) ? W1 : W2);
    float w0 = W[(size_t)k * Gg + col];
    float w1 = W[(size_t)(k + 1) * Gg + col];
    __nv_bfloat16 h0 = __float2bfloat16(w0), h1 = __float2bfloat16(w1);
    __nv_bfloat16 l0 = __float2bfloat16(w0 - __bfloat162float(h0));
    __nv_bfloat16 l1 = __float2bfloat16(w1 - __bfloat162float(h1));
    int blk = (mat == 2) ? (16 + tile) : (tile * 2 + mat);
    size_t base = ((size_t)cta * 16 + (size_t)(kc * 2 + mh)) * 24576
                  + (size_t)blk * 1024 + (size_t)(lane * 32);
    unsigned hp = (unsigned)*(unsigned short*)&h0 | ((unsigned)*(unsigned short*)&h1 << 16);
    unsigned lp = (unsigned)*(unsigned short*)&l0 | ((unsigned)*(unsigned short*)&l1 << 16);
    *(unsigned*)(g_Wf + base + reg * 4) = hp;
    *(unsigned*)(g_Wf + base + 16 + reg * 4) = lp;
}

// ---------------- GEMM: C = A[M,K]@B[K,N] + bias (proven) --------------------
__global__ void __launch_bounds__(256) sgemm_bias(
        const float* __restrict__ A, const float* __restrict__ Bm,
        const float* __restrict__ bias, float* __restrict__ C,
        int M, int N, int K)
{
    __shared__ float As[16][128];
    __shared__ float Bs[16][64];
    const int tid = threadIdx.x;
    const int bm = blockIdx.y * 128;
    const int bn = blockIdx.x * 64;
    const int tn = (tid & 15) * 4;
    const int tm = (tid >> 4) * 8;

    u64 acc[4][4];
#pragma unroll
    for (int i = 0; i < 4; ++i)
#pragma unroll
        for (int j = 0; j < 4; ++j) acc[i][j] = 0ULL;

    for (int k0 = 0; k0 < K; k0 += 16) {
#pragma unroll
        for (int i = 0; i < 2; ++i) {
            int fid = tid * 2 + i;
            int r = fid >> 2, kq = fid & 3;
            float4 v = *reinterpret_cast<const float4*>(A + (size_t)(bm + r) * K + k0 + kq * 4);
            As[kq * 4 + 0][r] = v.x;
            As[kq * 4 + 1][r] = v.y;
            As[kq * 4 + 2][r] = v.z;
            As[kq * 4 + 3][r] = v.w;
        }
        {
            int kr = tid >> 4, cq = (tid & 15) * 4;
            *reinterpret_cast<float4*>(&Bs[kr][cq]) =
                *reinterpret_cast<const float4*>(Bm + (size_t)(k0 + kr) * N + bn + cq);
        }
        __syncthreads();
#pragma unroll
        for (int kk = 0; kk < 16; ++kk) {
            ulonglong2 a01 = *reinterpret_cast<const ulonglong2*>(&As[kk][tm]);
            ulonglong2 a23 = *reinterpret_cast<const ulonglong2*>(&As[kk][tm + 4]);
            float4 bv = *reinterpret_cast<const float4*>(&Bs[kk][tn]);
            u64 bs0 = splat2(bv.x), bs1 = splat2(bv.y);
            u64 bs2 = splat2(bv.z), bs3 = splat2(bv.w);
            fma2(acc[0][0], a01.x, bs0); fma2(acc[0][1], a01.x, bs1);
            fma2(acc[0][2], a01.x, bs2); fma2(acc[0][3], a01.x, bs3);
            fma2(acc[1][0], a01.y, bs0); fma2(acc[1][1], a01.y, bs1);
            fma2(acc[1][2], a01.y, bs2); fma2(acc[1][3], a01.y, bs3);
            fma2(acc[2][0], a23.x, bs0); fma2(acc[2][1], a23.x, bs1);
            fma2(acc[2][2], a23.x, bs2); fma2(acc[2][3], a23.x, bs3);
            fma2(acc[3][0], a23.y, bs0); fma2(acc[3][1], a23.y, bs1);
            fma2(acc[3][2], a23.y, bs2); fma2(acc[3][3], a23.y, bs3);
        }
        __syncthreads();
    }

    float4 bb = *reinterpret_cast<const float4*>(bias + bn + tn);
#pragma unroll
    for (int mp = 0; mp < 4; ++mp) {
        float2 p0 = unpack2(acc[mp][0]);
        float2 p1 = unpack2(acc[mp][1]);
        float2 p2 = unpack2(acc[mp][2]);
        float2 p3 = unpack2(acc[mp][3]);
        int row0 = bm + tm + mp * 2;
        float4 o0 = make_float4(p0.x + bb.x, p1.x + bb.y, p2.x + bb.z, p3.x + bb.w);
        float4 o1 = make_float4(p0.y + bb.x, p1.y + bb.y, p2.y + bb.z, p3.y + bb.w);
        *reinterpret_cast<float4*>(C + (size_t)row0 * N + bn + tn) = o0;
        *reinterpret_cast<float4*>(C + (size_t)(row0 + 1) * N + bn + tn) = o1;
    }
}

__device__ __forceinline__ void grid_bar(unsigned target) {
    __syncthreads();
    const unsigned tid = threadIdx.x;
    if (tid == 0) { __threadfence(); st_rel(&g_arrive[blockIdx.x], target); }
    if (blockIdx.x == 0) {
        if (tid < NCTA) { while (ld_acq(&g_arrive[tid]) < target) {} }
        __syncthreads();
        if (tid == 0) st_rel(&g_go, target);
    }
    if (tid == 0) { while (ld_acq(&g_go) < target) {} }
    __syncthreads();
}

// ---------------- recurrence pieces ------------------------------------------
// stage one 128KB interleaved B buffer into smem [0,128K); one commit group
__device__ __forceinline__ void stage_B(unsigned sb, const char* src, int tid) {
#pragma unroll
    for (int p = 0; p < 16; ++p) {
        unsigned o = (unsigned)((p * 512 + tid) * 16);
        cp16(sb + o, src + o);
    }
    CPC;
}

// fused mat0+mat1: 16 blocks; B(h0) loaded once per tile, used by both A-frags
__device__ __forceinline__ void run_fused(float (&acc)[4][4], float (&accB)[4][4],
    bool a0, bool a1, int &cb, unsigned wring, const char* __restrict__ wg,
    unsigned sb, int kc, int lane)
{
    unsigned bf[4][4];
#pragma unroll 1
    for (int blk = 0; blk < 16; ++blk) {
        int pb = cb + 2; if (pb >= 24) pb -= 24;
        wpf(wring + (unsigned)((pb % 3) * 1024), wg + (size_t)pb * 1024, lane);
        CPW2;
        __syncwarp();
        int kt = kc * 8 + (blk >> 1);
        unsigned sa = wring + (unsigned)((cb % 3) * 1024 + lane * 32);
        if ((blk & 1) == 0) {
            if (a0 | a1) {
#pragma unroll
                for (int n8 = 0; n8 < 4; ++n8)
                    asm volatile("ld.shared.v4.b32 {%0,%1,%2,%3},[%4];"
                        : "=r"(bf[n8][0]), "=r"(bf[n8][1]),
                          "=r"(bf[n8][2]), "=r"(bf[n8][3])
                        : "r"(sb + (unsigned)(((kt * 4 + n8) * 32 + lane) * 16)));
            }
            if (a0) {
                unsigned ah[4], al[4];
                ldsA(sa, ah, al);
#pragma unroll
                for (int n8 = 0; n8 < 4; ++n8) {
                    mmabf(acc[n8], ah, bf[n8][0], bf[n8][1]);
                    mmabf(acc[n8], al, bf[n8][0], bf[n8][1]);
                    mmabf(acc[n8], ah, bf[n8][2], bf[n8][3]);
                }
            }
        } else if (a1) {
            unsigned ah[4], al[4];
            ldsA(sa, ah, al);
#pragma unroll
            for (int n8 = 0; n8 < 4; ++n8) {
                mmabf(accB[n8], ah, bf[n8][0], bf[n8][1]);
                mmabf(accB[n8], al, bf[n8][0], bf[n8][1]);
                mmabf(accB[n8], ah, bf[n8][2], bf[n8][3]);
            }
        }
        ++cb; if (cb >= 24) cb = 0;
    }
}

// mat2: 8 blocks over B(h1); tile0 waits own h1-stage group then block-syncs
__device__ __forceinline__ void run_mat2(float (&accB)[4][4], bool a2, int &cb,
    unsigned wring, const char* __restrict__ wg, unsigned sb, int kc, int lane)
{
#pragma unroll 1
    for (int tile = 0; tile < 8; ++tile) {
        int pb = cb + 2; if (pb >= 24) pb -= 24;
        wpf(wring + (unsigned)((pb % 3) * 1024), wg + (size_t)pb * 1024, lane);
        if (tile == 0) { CPW1; __syncthreads(); }
        else { CPW2; __syncwarp(); }
        if (a2) {
            int kt = kc * 8 + tile;
            unsigned sa = wring + (unsigned)((cb % 3) * 1024 + lane * 32);
            unsigned ah[4], al[4];
            ldsA(sa, ah, al);
#pragma unroll
            for (int n8 = 0; n8 < 4; ++n8) {
                unsigned b0, b1, b2, b3;
                asm volatile("ld.shared.v4.b32 {%0,%1,%2,%3},[%4];"
                    : "=r"(b0), "=r"(b1), "=r"(b2), "=r"(b3)
                    : "r"(sb + (unsigned)(((kt * 4 + n8) * 32 + lane) * 16)));
                mmabf(accB[n8], ah, b0, b1);
                mmabf(accB[n8], al, b0, b1);
                mmabf(accB[n8], ah, b2, b3);
            }
        }
        ++cb; if (cb >= 24) cb = 0;
    }
}

__device__ __forceinline__ void store_redH(float* red, float (&acc)[4][4],
                                           int kc, int mh, int lane)
{
    int r = lane >> 2, cq = (lane & 3) * 2;
#pragma unroll
    for (int n8 = 0; n8 < 4; ++n8) {
        int b = n8 * 8 + cq;
        int c = mh * 16 + r;
        *reinterpret_cast<float2*>(&red[kc * 1152 + c * 36 + b]) =
            make_float2(acc[n8][0], acc[n8][1]);
        *reinterpret_cast<float2*>(&red[kc * 1152 + (c + 8) * 36 + b]) =
            make_float2(acc[n8][2], acc[n8][3]);
    }
}

// write h into interleaved B-fragment buffer (hi at +0..7, lo at +8..15)
__device__ __forceinline__ void wr_frag(char* bb, int k, int b, float h) {
    int kt = k >> 4, kin = k & 15;
    int reg = kin >> 3, quad = (kin >> 1) & 3, half = kin & 1;
    unsigned off = (unsigned)((((kt * 4 + (b >> 3)) * 32) + (b & 7) * 4 + quad) * 16
                              + reg * 4 + half * 2);
    __nv_bfloat16 hh = __float2bfloat16(h);
    __nv_bfloat16 hl = __float2bfloat16(h - __bfloat162float(hh));
    *(__nv_bfloat16*)(bb + off) = hh;
    *(__nv_bfloat16*)(bb + off + 8) = hl;
}

// ---------------- persistent 2-layer LSTM recurrence (HMMA) ------------------
// SMEM: [0,128K) B interleaved  [128K,176K) W ring 16x3KB  [176K,212K) red
__global__ void __launch_bounds__(512, 1) lstm_hm2(const float* __restrict__ b1v)
{
    extern __shared__ char smc[];
    float* red = reinterpret_cast<float*>(smc + 180224);
    const unsigned sb = smem_u32(smc);

    const int tid = threadIdx.x, lane = tid & 31, wid = tid >> 5;
    const int kc = wid >> 1, mh = wid & 1;
    const int cta = blockIdx.x, jbase = cta * 8;
    const unsigned wring = sb + 131072u + (unsigned)(wid * 3072);
    const char* wg = g_Wf + ((size_t)cta * 16 + (size_t)(kc * 2 + mh)) * 24576;

    const int gb = tid >> 3, gj = tid & 7;
    float c0s = 0.f, c1s = 0.f;
    float bias1[4];
    if (tid < 256) {
#pragma unroll
        for (int g = 0; g < 4; ++g) bias1[g] = b1v[g * Hh + jbase + gj];
    }

    int cb = 0;
    wpf(wring, wg, lane);
    wpf(wring + 1024, wg + 1024, lane);

    for (int s = 0; s <= Tt; ++s) {
        const int rb = (s + 1) & 1;
        const int wb = s & 1;

        stage_B(sb, g_Bf[0][rb], tid);      // h0(s-1) interleaved frags
        CPW0;
        __syncthreads();

        float xw[4];
        if (tid < 256 && s < Tt) {
#pragma unroll
            for (int g = 0; g < 4; ++g)
                xw[g] = __ldcg(&g_XW[((size_t)gb * Tt + s) * Gg + g * Hh + jbase + gj]);
        }

        float acc[4][4], accB[4][4];
#pragma unroll
        for (int i = 0; i < 4; ++i)
#pragma unroll
            for (int j = 0; j < 4; ++j) { acc[i][j] = 0.f; accB[i][j] = 0.f; }

        run_fused(acc, accB, s < Tt, s > 0, cb, wring, wg, sb, kc, lane);
        if (s < Tt) store_redH(red, acc, kc, mh, lane);
        __syncthreads();                     // red ready, all B(h0) reads done

        stage_B(sb, g_Bf[1][rb], tid);       // h1(s-2), overlapped with reduction

        float z0[4];
        if (tid < 256 && s < Tt) {
#pragma unroll
            for (int g = 0; g < 4; ++g) {
                float t = xw[g];
#pragma unroll
                for (int kk = 0; kk < 8; ++kk)
                    t += red[kk * 1152 + (g * 8 + gj) * 36 + gb];
                z0[g] = t;
            }
        }
        __syncthreads();                     // red free for mat2 store

        run_mat2(accB, s > 0, cb, wring, wg, sb, kc, lane);
        if (s > 0) store_redH(red, accB, kc, mh, lane);
        __syncthreads();

        if (tid < 256) {
            if (s < Tt) {
                float I = sig_(z0[0]), F = sig_(z0[1]);
                float G = tanh_(z0[2]), O = sig_(z0[3]);
                c0s = F * c0s + I * G;
                float h = O * tanh_(c0s);
                wr_frag(g_Bf[0][wb], jbase + gj, gb, h);
            }
            if (s > 0) {
                float z1[4];
#pragma unroll
                for (int g = 0; g < 4; ++g) {
                    float t = bias1[g];
#pragma unroll
                    for (int kk = 0; kk < 8; ++kk)
                        t += red[kk * 1152 + (g * 8 + gj) * 36 + gb];
                    z1[g] = t;
                }
                float I = sig_(z1[0]), F = sig_(z1[1]);
                float G = tanh_(z1[2]), O = sig_(z1[3]);
                c1s = F * c1s + I * G;
                float h = O * tanh_(c1s);
                wr_frag(g_Bf[1][wb], jbase + gj, gb, h);
                g_Y[((size_t)gb * Tt + (s - 1)) * Hh + jbase + gj] = h;
            }
        }
        grid_bar((unsigned)(s + 1));
    }
    CPW0;
}

// ---------------- launch ------------------------------------------------------
extern "C" void kernel_launch(void* const* d_in, const int* in_sizes, int n_in,
                              void* d_out, int out_size)
{
    const float* x   = (const float*)d_in[0];
    const float* Wx0 = (const float*)d_in[1];
    const float* Wh0 = (const float*)d_in[2];
    const float* b0v = (const float*)d_in[3];
    const float* Wx1 = (const float*)d_in[4];
    const float* Wh1 = (const float*)d_in[5];
    const float* b1v = (const float*)d_in[6];
    const float* Wd  = (const float*)d_in[7];
    const float* bdv = (const float*)d_in[8];
    float* out = (float*)d_out;

    float* xw; cudaGetSymbolAddress((void**)&xw, g_XW);
    float* yv; cudaGetSymbolAddress((void**)&yv, g_Y);

    cudaFuncSetAttribute(lstm_hm2, cudaFuncAttributeMaxDynamicSharedMemorySize, SMT);

    init_state<<<64, 512>>>();
    pack_hmma<<<24576, 256>>>(Wh0, Wx1, Wh1);

    sgemm_bias<<<dim3(Gg / 64, (Bb * Tt) / 128), 256>>>(x, Wx0, b0v, xw,
                                                        Bb * Tt, Gg, Dd);
    lstm_hm2<<<NCTA, 512, SMT>>>(b1v);

    sgemm_bias<<<dim3(Oo / 64, (Bb * Tt) / 128), 256>>>(yv, Wd, bdv, out,
                                                        Bb * Tt, Oo, Hh);
}

// round 15
// speedup vs baseline: 8.5721x; 1.1455x over previous
#include <cuda_runtime.h>
#include <cuda_bf16.h>
#include <cstdint>

typedef unsigned long long u64;

#define Bb 32
#define Tt 512
#define Dd 512
#define Hh 1024
#define Gg 4096
#define Oo 512
#define NCTA 128
#define SMT 217088

__device__ float g_XW[(size_t)Bb * Tt * Gg];
__device__ char  g_Wf[(size_t)128 * 16 * 24576];   // 48MB recurrence A-frag images
__device__ char  g_Bf[2][2][131072];               // [layer][buf] h frags (hi|lo)
__device__ char  g_Apx[(size_t)33554432];          // x packed A-frags (hi|lo)
__device__ char  g_Ypk[(size_t)67108864];          // Y packed A-frags (hi|lo)
__device__ char  g_Bx [(size_t)8388608];           // Wx0 packed B-frags
__device__ char  g_Bd [(size_t)2097152];           // Wd  packed B-frags
__device__ unsigned g_arrive[NCTA];
__device__ unsigned g_go;

// ---------------- helpers ----------------------------------------------------
__device__ __forceinline__ unsigned smem_u32(const void* p) {
    unsigned a;
    asm("{ .reg .u64 t; cvta.to.shared.u64 t, %1; cvt.u32.u64 %0, t; }"
        : "=r"(a) : "l"(p));
    return a;
}
__device__ __forceinline__ void st_rel(unsigned* p, unsigned v) {
    asm volatile("st.release.gpu.u32 [%0],%1;" :: "l"(p), "r"(v) : "memory");
}
__device__ __forceinline__ unsigned ld_acq(const unsigned* p) {
    unsigned v; asm volatile("ld.acquire.gpu.u32 %0,[%1];" : "=r"(v) : "l"(p) : "memory");
    return v;
}
__device__ __forceinline__ void cp16(unsigned d, const char* s) {
    asm volatile("cp.async.cg.shared.global [%0],[%1],16;" :: "r"(d), "l"(s) : "memory");
}
#define CPC  asm volatile("cp.async.commit_group;" ::: "memory")
#define CPW0 asm volatile("cp.async.wait_group 0;" ::: "memory")
#define CPW1 asm volatile("cp.async.wait_group 1;" ::: "memory")
#define CPW2 asm volatile("cp.async.wait_group 2;" ::: "memory")
__device__ __forceinline__ void wpf(unsigned dst, const char* src, int lane) {
    asm volatile("cp.async.cg.shared.global [%0],[%1],16;\n\t"
                 "cp.async.cg.shared.global [%2],[%3],16;\n\t"
                 "cp.async.commit_group;"
                 :: "r"(dst + lane * 16), "l"(src + lane * 16),
                    "r"(dst + 512 + lane * 16), "l"(src + 512 + lane * 16)
                 : "memory");
}
__device__ __forceinline__ void mmabf(float* d, const unsigned* a, unsigned b0, unsigned b1) {
    asm volatile("mma.sync.aligned.m16n8k16.row.col.f32.bf16.bf16.f32 "
                 "{%0,%1,%2,%3},{%4,%5,%6,%7},{%8,%9},{%0,%1,%2,%3};"
                 : "+f"(d[0]), "+f"(d[1]), "+f"(d[2]), "+f"(d[3])
                 : "r"(a[0]), "r"(a[1]), "r"(a[2]), "r"(a[3]), "r"(b0), "r"(b1));
}
__device__ __forceinline__ void ldsA(unsigned sa, unsigned* ah, unsigned* al) {
    asm volatile("ld.shared.v4.b32 {%0,%1,%2,%3},[%4];"
        : "=r"(ah[0]), "=r"(ah[1]), "=r"(ah[2]), "=r"(ah[3]) : "r"(sa));
    asm volatile("ld.shared.v4.b32 {%0,%1,%2,%3},[%4];"
        : "=r"(al[0]), "=r"(al[1]), "=r"(al[2]), "=r"(al[3]) : "r"(sa + 16));
}
__device__ __forceinline__ float sig_(float x) { return 1.f / (1.f + __expf(-x)); }
__device__ __forceinline__ float tanh_(float x) {
    float xx = fminf(fmaxf(x, -15.f), 15.f);
    float e = __expf(-2.f * xx);
    return (1.f - e) / (1.f + e);
}
__device__ __forceinline__ void split2(float w0, float w1, unsigned &hp, unsigned &lp) {
    __nv_bfloat16 h0 = __float2bfloat16(w0), h1 = __float2bfloat16(w1);
    __nv_bfloat16 l0 = __float2bfloat16(w0 - __bfloat162float(h0));
    __nv_bfloat16 l1 = __float2bfloat16(w1 - __bfloat162float(h1));
    hp = (unsigned)*(unsigned short*)&h0 | ((unsigned)*(unsigned short*)&h1 << 16);
    lp = (unsigned)*(unsigned short*)&l0 | ((unsigned)*(unsigned short*)&l1 << 16);
}

__global__ void init_state() {
    int i = blockIdx.x * blockDim.x + threadIdx.x;
    uint4* bf = reinterpret_cast<uint4*>(&g_Bf[0][0][0]);
    if (i < 32768) bf[i] = make_uint4(0, 0, 0, 0);
    if (i < NCTA) g_arrive[i] = 0;
    if (i == 0) g_go = 0;
}

// ---------------- pack: recurrence W -> A-frag images (proven) ---------------
__global__ void pack_hmma(const float* __restrict__ W0, const float* __restrict__ W1,
                          const float* __restrict__ W2)
{
    unsigned id = blockIdx.x * blockDim.x + threadIdx.x;
    int reg = id & 3, lane = (id >> 2) & 31, tile = (id >> 7) & 7;
    int mh = (id >> 10) & 1, kc = (id >> 11) & 7;
    unsigned rm = id >> 14;
    int mat = rm % 3, cta = (int)(rm / 3);
    int r = lane >> 2, cq = (lane & 3) * 2;
    int m = mh * 16 + r + (reg & 1) * 8;
    int k = kc * 128 + tile * 16 + cq + ((reg >> 1) & 1) * 8;
    int col = (m >> 3) * Hh + cta * 8 + (m & 7);
    const float* W = (mat == 0) ? W0 : ((mat == 1) ? W1 : W2);
    unsigned hp, lp;
    split2(W[(size_t)k * Gg + col], W[(size_t)(k + 1) * Gg + col], hp, lp);
    int blk = (mat == 2) ? (16 + tile) : (tile * 2 + mat);
    size_t base = ((size_t)cta * 16 + (size_t)(kc * 2 + mh)) * 24576
                  + (size_t)blk * 1024 + (size_t)(lane * 32);
    *(unsigned*)(g_Wf + base + reg * 4) = hp;
    *(unsigned*)(g_Wf + base + 16 + reg * 4) = lp;
}

// ---------------- pack: GEMM B [K,N] fp32 -> B-frag hi|lo images -------------
// dst frag layout: ((nblk*KT+kt)*8+n8)*512 + lane*16 + [hi 8B | lo 8B]
__global__ void pack_Bw(const float* __restrict__ B, char* __restrict__ dst,
                        int KT, int N)
{
    unsigned id = blockIdx.x * blockDim.x + threadIdx.x;
    int reg = id & 1, lane = (id >> 1) & 31, n8 = (id >> 6) & 7;
    unsigned i9 = id >> 9;
    int kt = (int)(i9 % (unsigned)KT), nblk = (int)(i9 / (unsigned)KT);
    int n = nblk * 64 + n8 * 8 + (lane >> 2);
    int k = kt * 16 + reg * 8 + (lane & 3) * 2;
    unsigned hp, lp;
    split2(B[(size_t)k * N + n], B[(size_t)(k + 1) * N + n], hp, lp);
    size_t base = ((size_t)(nblk * KT + kt) * 8 + n8) * 512 + (size_t)(lane * 16);
    *(unsigned*)(dst + base + reg * 4) = hp;
    *(unsigned*)(dst + base + 8 + reg * 4) = lp;
}

// ---------------- cvt: A [M,K] fp32 -> A-frag hi|lo images -------------------
// dst: ((mblk*KT+kt)*8+mf)*1024 + lane*32 + [hi 16B | lo 16B]
__global__ void cvt_Ax(const float* __restrict__ A, char* __restrict__ dst,
                       int KT, int K)
{
    unsigned id = blockIdx.x * blockDim.x + threadIdx.x;
    int reg = id & 3, lane = (id >> 2) & 31, mf = (id >> 7) & 7;
    unsigned i10 = id >> 10;
    int kt = (int)(i10 % (unsigned)KT), mblk = (int)(i10 / (unsigned)KT);
    int m = mblk * 128 + mf * 16 + (lane >> 2) + (reg & 1) * 8;
    int k = kt * 16 + (lane & 3) * 2 + ((reg >> 1) & 1) * 8;
    unsigned hp, lp;
    split2(A[(size_t)m * K + k], A[(size_t)m * K + k + 1], hp, lp);
    size_t base = ((size_t)(mblk * KT + kt) * 8 + mf) * 1024 + (size_t)(lane * 32);
    *(unsigned*)(dst + base + reg * 4) = hp;
    *(unsigned*)(dst + base + 16 + reg * 4) = lp;
}

// ---------------- HMMA GEMM: C[M,N] = A@B + bias (packed frag inputs) --------
// 128x64 CTA tile, 8 warps: mw=wid&3 (m frags mw, mw+4), nw=wid>>2 (n8 nw*4..+3)
__global__ void __launch_bounds__(256) hmma_gemm(
        const char* __restrict__ Apk, const char* __restrict__ Bpk,
        const float* __restrict__ bias, float* __restrict__ C, int KT, int N)
{
    __shared__ char As[2][8192];
    __shared__ char Bs[2][4096];
    const int tid = threadIdx.x, lane = tid & 31, wid = tid >> 5;
    const int mw = wid & 3, nw = wid >> 2;
    const int mblk = blockIdx.y, nblk = blockIdx.x;
    const char* Agp = Apk + (size_t)mblk * KT * 8192;
    const char* Bgp = Bpk + (size_t)nblk * KT * 4096;
    const unsigned sa0 = smem_u32(As[0]), sa1 = smem_u32(As[1]);
    const unsigned sb0 = smem_u32(Bs[0]), sb1 = smem_u32(Bs[1]);

    float acc[2][4][4];
#pragma unroll
    for (int i = 0; i < 2; ++i)
#pragma unroll
        for (int j = 0; j < 4; ++j)
#pragma unroll
            for (int c = 0; c < 4; ++c) acc[i][j][c] = 0.f;

    // stage kt=0 into buf0
    cp16(sa0 + tid * 32, Agp + tid * 32);
    cp16(sa0 + tid * 32 + 16, Agp + tid * 32 + 16);
    cp16(sb0 + tid * 16, Bgp + tid * 16);
    CPC;

#pragma unroll 1
    for (int kt = 0; kt < KT; ++kt) {
        if (kt + 1 < KT) {
            unsigned da = (kt & 1) ? sa0 : sa1;
            unsigned db = (kt & 1) ? sb0 : sb1;
            const char* pa = Agp + (size_t)(kt + 1) * 8192;
            const char* pb = Bgp + (size_t)(kt + 1) * 4096;
            cp16(da + tid * 32, pa + tid * 32);
            cp16(da + tid * 32 + 16, pa + tid * 32 + 16);
            cp16(db + tid * 16, pb + tid * 16);
            CPC;
            CPW1;
        } else {
            CPW0;
        }
        __syncthreads();
        unsigned ab = (kt & 1) ? sa1 : sa0;
        unsigned bbs = (kt & 1) ? sb1 : sb0;
#pragma unroll
        for (int mi = 0; mi < 2; ++mi) {
            unsigned ah[4], al[4];
            ldsA(ab + (unsigned)((mw + mi * 4) * 1024 + lane * 32), ah, al);
#pragma unroll
            for (int n8 = 0; n8 < 4; ++n8) {
                unsigned bh0, bh1, bl0, bl1;
                asm volatile("ld.shared.v4.b32 {%0,%1,%2,%3},[%4];"
                    : "=r"(bh0), "=r"(bh1), "=r"(bl0), "=r"(bl1)
                    : "r"(bbs + (unsigned)((nw * 4 + n8) * 512 + lane * 16)));
                mmabf(acc[mi][n8], ah, bh0, bh1);
                mmabf(acc[mi][n8], al, bh0, bh1);
                mmabf(acc[mi][n8], ah, bl0, bl1);
            }
        }
        __syncthreads();
    }

#pragma unroll
    for (int mi = 0; mi < 2; ++mi) {
        int m0 = mblk * 128 + (mw + mi * 4) * 16 + (lane >> 2);
#pragma unroll
        for (int n8 = 0; n8 < 4; ++n8) {
            int n0 = nblk * 64 + (nw * 4 + n8) * 8 + (lane & 3) * 2;
            float2 bv = *reinterpret_cast<const float2*>(&bias[n0]);
            *reinterpret_cast<float2*>(&C[(size_t)m0 * N + n0]) =
                make_float2(acc[mi][n8][0] + bv.x, acc[mi][n8][1] + bv.y);
            *reinterpret_cast<float2*>(&C[(size_t)(m0 + 8) * N + n0]) =
                make_float2(acc[mi][n8][2] + bv.x, acc[mi][n8][3] + bv.y);
        }
    }
}

__device__ __forceinline__ void grid_bar(unsigned target) {
    __syncthreads();
    const unsigned tid = threadIdx.x;
    if (tid == 0) { __threadfence(); st_rel(&g_arrive[blockIdx.x], target); }
    if (blockIdx.x == 0) {
        if (tid < NCTA) { while (ld_acq(&g_arrive[tid]) < target) {} }
        __syncthreads();
        if (tid == 0) st_rel(&g_go, target);
    }
    if (tid == 0) { while (ld_acq(&g_go) < target) {} }
    __syncthreads();
}

// ---------------- recurrence pieces (proven R13) ------------------------------
__device__ __forceinline__ void stage_B(unsigned sb, const char* src, int tid) {
#pragma unroll
    for (int p = 0; p < 16; ++p) {
        unsigned o = (unsigned)((p * 512 + tid) * 16);
        cp16(sb + o, src + o);
    }
    CPC;
}

__device__ __forceinline__ void run_fused(float (&acc)[4][4], float (&accB)[4][4],
    bool a0, bool a1, int &cb, unsigned wring, const char* __restrict__ wg,
    unsigned sb, int kc, int lane)
{
    unsigned bf[4][4];
#pragma unroll 1
    for (int blk = 0; blk < 16; ++blk) {
        int pb = cb + 2; if (pb >= 24) pb -= 24;
        wpf(wring + (unsigned)((pb % 3) * 1024), wg + (size_t)pb * 1024, lane);
        CPW2;
        __syncwarp();
        int kt = kc * 8 + (blk >> 1);
        unsigned sa = wring + (unsigned)((cb % 3) * 1024 + lane * 32);
        if ((blk & 1) == 0) {
            if (a0 | a1) {
#pragma unroll
                for (int n8 = 0; n8 < 4; ++n8)
                    asm volatile("ld.shared.v4.b32 {%0,%1,%2,%3},[%4];"
                        : "=r"(bf[n8][0]), "=r"(bf[n8][1]),
                          "=r"(bf[n8][2]), "=r"(bf[n8][3])
                        : "r"(sb + (unsigned)(((kt * 4 + n8) * 32 + lane) * 16)));
            }
            if (a0) {
                unsigned ah[4], al[4];
                ldsA(sa, ah, al);
#pragma unroll
                for (int n8 = 0; n8 < 4; ++n8) {
                    mmabf(acc[n8], ah, bf[n8][0], bf[n8][1]);
                    mmabf(acc[n8], al, bf[n8][0], bf[n8][1]);
                    mmabf(acc[n8], ah, bf[n8][2], bf[n8][3]);
                }
            }
        } else if (a1) {
            unsigned ah[4], al[4];
            ldsA(sa, ah, al);
#pragma unroll
            for (int n8 = 0; n8 < 4; ++n8) {
                mmabf(accB[n8], ah, bf[n8][0], bf[n8][1]);
                mmabf(accB[n8], al, bf[n8][0], bf[n8][1]);
                mmabf(accB[n8], ah, bf[n8][2], bf[n8][3]);
            }
        }
        ++cb; if (cb >= 24) cb = 0;
    }
}

__device__ __forceinline__ void run_mat2(float (&accB)[4][4], bool a2, int &cb,
    unsigned wring, const char* __restrict__ wg, unsigned sb, int kc, int lane)
{
#pragma unroll 1
    for (int tile = 0; tile < 8; ++tile) {
        int pb = cb + 2; if (pb >= 24) pb -= 24;
        wpf(wring + (unsigned)((pb % 3) * 1024), wg + (size_t)pb * 1024, lane);
        if (tile == 0) { CPW1; __syncthreads(); }
        else { CPW2; __syncwarp(); }
        if (a2) {
            int kt = kc * 8 + tile;
            unsigned sa = wring + (unsigned)((cb % 3) * 1024 + lane * 32);
            unsigned ah[4], al[4];
            ldsA(sa, ah, al);
#pragma unroll
            for (int n8 = 0; n8 < 4; ++n8) {
                unsigned b0, b1, b2, b3;
                asm volatile("ld.shared.v4.b32 {%0,%1,%2,%3},[%4];"
                    : "=r"(b0), "=r"(b1), "=r"(b2), "=r"(b3)
                    : "r"(sb + (unsigned)(((kt * 4 + n8) * 32 + lane) * 16)));
                mmabf(accB[n8], ah, b0, b1);
                mmabf(accB[n8], al, b0, b1);
                mmabf(accB[n8], ah, b2, b3);
            }
        }
        ++cb; if (cb >= 24) cb = 0;
    }
}

__device__ __forceinline__ void store_redH(float* red, float (&acc)[4][4],
                                           int kc, int mh, int lane)
{
    int r = lane >> 2, cq = (lane & 3) * 2;
#pragma unroll
    for (int n8 = 0; n8 < 4; ++n8) {
        int b = n8 * 8 + cq;
        int c = mh * 16 + r;
        *reinterpret_cast<float2*>(&red[kc * 1152 + c * 36 + b]) =
            make_float2(acc[n8][0], acc[n8][1]);
        *reinterpret_cast<float2*>(&red[kc * 1152 + (c + 8) * 36 + b]) =
            make_float2(acc[n8][2], acc[n8][3]);
    }
}

__device__ __forceinline__ void wr_frag(char* bb, int k, int b, float h) {
    int kt = k >> 4, kin = k & 15;
    int reg = kin >> 3, quad = (kin >> 1) & 3, half = kin & 1;
    unsigned off = (unsigned)((((kt * 4 + (b >> 3)) * 32) + (b & 7) * 4 + quad) * 16
                              + reg * 4 + half * 2);
    __nv_bfloat16 hh = __float2bfloat16(h);
    __nv_bfloat16 hl = __float2bfloat16(h - __bfloat162float(hh));
    *(__nv_bfloat16*)(bb + off) = hh;
    *(__nv_bfloat16*)(bb + off + 8) = hl;
}

// write h into Y packed A-frag image (m = gb*Tt+t, k = j), KT=64
__device__ __forceinline__ void wr_Ypk(int m, int k, float h) {
    int mblk = m >> 7, mi = m & 127, mf = mi >> 4, r16 = mi & 15;
    int kt = k >> 4, ki = k & 15;
    int reg = (r16 >> 3) | ((ki >> 3) << 1);
    int ln = (r16 & 7) * 4 + ((ki & 7) >> 1);
    size_t base = ((size_t)(mblk * 64 + kt) * 8 + mf) * 1024 + (size_t)(ln * 32);
    __nv_bfloat16 hh = __float2bfloat16(h);
    __nv_bfloat16 hl = __float2bfloat16(h - __bfloat162float(hh));
    char* p = g_Ypk + base + reg * 4 + (ki & 1) * 2;
    *(__nv_bfloat16*)p = hh;
    *(__nv_bfloat16*)(p + 16) = hl;
}

// ---------------- persistent 2-layer LSTM recurrence (HMMA, proven) ----------
__global__ void __launch_bounds__(512, 1) lstm_hm2(const float* __restrict__ b1v)
{
    extern __shared__ char smc[];
    float* red = reinterpret_cast<float*>(smc + 180224);
    const unsigned sb = smem_u32(smc);

    const int tid = threadIdx.x, lane = tid & 31, wid = tid >> 5;
    const int kc = wid >> 1, mh = wid & 1;
    const int cta = blockIdx.x, jbase = cta * 8;
    const unsigned wring = sb + 131072u + (unsigned)(wid * 3072);
    const char* wg = g_Wf + ((size_t)cta * 16 + (size_t)(kc * 2 + mh)) * 24576;

    const int gb = tid >> 3, gj = tid & 7;
    float c0s = 0.f, c1s = 0.f;
    float bias1[4];
    if (tid < 256) {
#pragma unroll
        for (int g = 0; g < 4; ++g) bias1[g] = b1v[g * Hh + jbase + gj];
    }

    int cb = 0;
    wpf(wring, wg, lane);
    wpf(wring + 1024, wg + 1024, lane);

    for (int s = 0; s <= Tt; ++s) {
        const int rb = (s + 1) & 1;
        const int wb = s & 1;

        stage_B(sb, g_Bf[0][rb], tid);      // h0(s-1) frags

        float xw[4];                         // overlapped with stage wait
        if (tid < 256 && s < Tt) {
#pragma unroll
            for (int g = 0; g < 4; ++g)
                xw[g] = __ldcg(&g_XW[((size_t)gb * Tt + s) * Gg + g * Hh + jbase + gj]);
        }
        CPW0;
        __syncthreads();

        float acc[4][4], accB[4][4];
#pragma unroll
        for (int i = 0; i < 4; ++i)
#pragma unroll
            for (int j = 0; j < 4; ++j) { acc[i][j] = 0.f; accB[i][j] = 0.f; }

        run_fused(acc, accB, s < Tt, s > 0, cb, wring, wg, sb, kc, lane);
        if (s < Tt) store_redH(red, acc, kc, mh, lane);
        __syncthreads();

        stage_B(sb, g_Bf[1][rb], tid);       // h1(s-2), overlapped with reduction

        float z0[4];
        if (tid < 256 && s < Tt) {
#pragma unroll
            for (int g = 0; g < 4; ++g) {
                float t = xw[g];
#pragma unroll
                for (int kk = 0; kk < 8; ++kk)
                    t += red[kk * 1152 + (g * 8 + gj) * 36 + gb];
                z0[g] = t;
            }
        }
        __syncthreads();

        run_mat2(accB, s > 0, cb, wring, wg, sb, kc, lane);
        if (s > 0) store_redH(red, accB, kc, mh, lane);
        __syncthreads();

        if (tid < 256) {
            if (s < Tt) {
                float I = sig_(z0[0]), F = sig_(z0[1]);
                float G = tanh_(z0[2]), O = sig_(z0[3]);
                c0s = F * c0s + I * G;
                float h = O * tanh_(c0s);
                wr_frag(g_Bf[0][wb], jbase + gj, gb, h);
            }
            if (s > 0) {
                float z1[4];
#pragma unroll
                for (int g = 0; g < 4; ++g) {
                    float t = bias1[g];
#pragma unroll
                    for (int kk = 0; kk < 8; ++kk)
                        t += red[kk * 1152 + (g * 8 + gj) * 36 + gb];
                    z1[g] = t;
                }
                float I = sig_(z1[0]), F = sig_(z1[1]);
                float G = tanh_(z1[2]), O = sig_(z1[3]);
                c1s = F * c1s + I * G;
                float h = O * tanh_(c1s);
                wr_frag(g_Bf[1][wb], jbase + gj, gb, h);
                wr_Ypk(gb * Tt + (s - 1), jbase + gj, h);
            }
        }
        grid_bar((unsigned)(s + 1));
    }
    CPW0;
}

// ---------------- launch ------------------------------------------------------
extern "C" void kernel_launch(void* const* d_in, const int* in_sizes, int n_in,
                              void* d_out, int out_size)
{
    const float* x   = (const float*)d_in[0];
    const float* Wx0 = (const float*)d_in[1];
    const float* Wh0 = (const float*)d_in[2];
    const float* b0v = (const float*)d_in[3];
    const float* Wx1 = (const float*)d_in[4];
    const float* Wh1 = (const float*)d_in[5];
    const float* b1v = (const float*)d_in[6];
    const float* Wd  = (const float*)d_in[7];
    const float* bdv = (const float*)d_in[8];
    float* out = (float*)d_out;

    float* xw;  cudaGetSymbolAddress((void**)&xw,  g_XW);
    char*  apx; cudaGetSymbolAddress((void**)&apx, g_Apx);
    char*  ypk; cudaGetSymbolAddress((void**)&ypk, g_Ypk);
    char*  bx;  cudaGetSymbolAddress((void**)&bx,  g_Bx);
    char*  bd;  cudaGetSymbolAddress((void**)&bd,  g_Bd);

    cudaFuncSetAttribute(lstm_hm2, cudaFuncAttributeMaxDynamicSharedMemorySize, SMT);

    init_state<<<64, 512>>>();
    pack_hmma<<<24576, 256>>>(Wh0, Wx1, Wh1);
    pack_Bw<<<4096, 256>>>(Wx0, bx, Dd / 16, Gg);       // Wx0 [512,4096]
    pack_Bw<<<1024, 256>>>(Wd,  bd, Hh / 16, Oo);       // Wd  [1024,512]
    cvt_Ax<<<16384, 256>>>(x, apx, Dd / 16, Dd);        // x   [16384,512]

    // XW = x @ Wx0 + b0   [16384,4096]
    hmma_gemm<<<dim3(Gg / 64, (Bb * Tt) / 128), 256>>>(apx, bx, b0v, xw,
                                                       Dd / 16, Gg);
    lstm_hm2<<<NCTA, 512, SMT>>>(b1v);

    // out = Y @ Wd + bd   [16384,512]
    hmma_gemm<<<dim3(Oo / 64, (Bb * Tt) / 128), 256>>>(ypk, bd, bdv, out,
                                                       Hh / 16, Oo);
}

// round 16
// speedup vs baseline: 8.7770x; 1.0239x over previous
#include <cuda_runtime.h>
#include <cuda_bf16.h>
#include <cstdint>

typedef unsigned long long u64;

#define Bb 32
#define Tt 512
#define Dd 512
#define Hh 1024
#define Gg 4096
#define Oo 512
#define NCTA 128
#define SMT 217088

__device__ float g_XW[(size_t)Bb * Tt * Gg];
__device__ char  g_Wf[(size_t)128 * 16 * 24576];   // 48MB recurrence A-frag images
__device__ char  g_Bf[2][2][131072];               // [layer][buf] h frags (hi|lo)
__device__ char  g_Apx[(size_t)33554432];          // x packed A-frags (hi|lo)
__device__ char  g_Ypk[(size_t)67108864];          // Y packed A-frags (hi|lo)
__device__ char  g_Bx [(size_t)8388608];           // Wx0 packed B-frags
__device__ char  g_Bd [(size_t)2097152];           // Wd  packed B-frags
__device__ unsigned g_arrive[NCTA];
__device__ unsigned g_go;

// ---------------- helpers ----------------------------------------------------
__device__ __forceinline__ unsigned smem_u32(const void* p) {
    unsigned a;
    asm("{ .reg .u64 t; cvta.to.shared.u64 t, %1; cvt.u32.u64 %0, t; }"
        : "=r"(a) : "l"(p));
    return a;
}
__device__ __forceinline__ void st_rel(unsigned* p, unsigned v) {
    asm volatile("st.release.gpu.u32 [%0],%1;" :: "l"(p), "r"(v) : "memory");
}
__device__ __forceinline__ unsigned ld_acq(const unsigned* p) {
    unsigned v; asm volatile("ld.acquire.gpu.u32 %0,[%1];" : "=r"(v) : "l"(p) : "memory");
    return v;
}
__device__ __forceinline__ void cp16(unsigned d, const char* s) {
    asm volatile("cp.async.cg.shared.global [%0],[%1],16;" :: "r"(d), "l"(s) : "memory");
}
#define CPC  asm volatile("cp.async.commit_group;" ::: "memory")
#define CPW0 asm volatile("cp.async.wait_group 0;" ::: "memory")
#define CPW1 asm volatile("cp.async.wait_group 1;" ::: "memory")
#define CPW2 asm volatile("cp.async.wait_group 2;" ::: "memory")
#define PAIRBAR(id) asm volatile("bar.sync %0, 64;" :: "r"(id) : "memory")
__device__ __forceinline__ void wpf(unsigned dst, const char* src, int lane) {
    asm volatile("cp.async.cg.shared.global [%0],[%1],16;\n\t"
                 "cp.async.cg.shared.global [%2],[%3],16;\n\t"
                 "cp.async.commit_group;"
                 :: "r"(dst + lane * 16), "l"(src + lane * 16),
                    "r"(dst + 512 + lane * 16), "l"(src + 512 + lane * 16)
                 : "memory");
}
__device__ __forceinline__ void mmabf(float* d, const unsigned* a, unsigned b0, unsigned b1) {
    asm volatile("mma.sync.aligned.m16n8k16.row.col.f32.bf16.bf16.f32 "
                 "{%0,%1,%2,%3},{%4,%5,%6,%7},{%8,%9},{%0,%1,%2,%3};"
                 : "+f"(d[0]), "+f"(d[1]), "+f"(d[2]), "+f"(d[3])
                 : "r"(a[0]), "r"(a[1]), "r"(a[2]), "r"(a[3]), "r"(b0), "r"(b1));
}
__device__ __forceinline__ void ldsA(unsigned sa, unsigned* ah, unsigned* al) {
    asm volatile("ld.shared.v4.b32 {%0,%1,%2,%3},[%4];"
        : "=r"(ah[0]), "=r"(ah[1]), "=r"(ah[2]), "=r"(ah[3]) : "r"(sa));
    asm volatile("ld.shared.v4.b32 {%0,%1,%2,%3},[%4];"
        : "=r"(al[0]), "=r"(al[1]), "=r"(al[2]), "=r"(al[3]) : "r"(sa + 16));
}
__device__ __forceinline__ float sig_(float x) { return 1.f / (1.f + __expf(-x)); }
__device__ __forceinline__ float tanh_(float x) {
    float xx = fminf(fmaxf(x, -15.f), 15.f);
    float e = __expf(-2.f * xx);
    return (1.f - e) / (1.f + e);
}
__device__ __forceinline__ void split2(float w0, float w1, unsigned &hp, unsigned &lp) {
    __nv_bfloat16 h0 = __float2bfloat16(w0), h1 = __float2bfloat16(w1);
    __nv_bfloat16 l0 = __float2bfloat16(w0 - __bfloat162float(h0));
    __nv_bfloat16 l1 = __float2bfloat16(w1 - __bfloat162float(h1));
    hp = (unsigned)*(unsigned short*)&h0 | ((unsigned)*(unsigned short*)&h1 << 16);
    lp = (unsigned)*(unsigned short*)&l0 | ((unsigned)*(unsigned short*)&l1 << 16);
}

__global__ void init_state() {
    int i = blockIdx.x * blockDim.x + threadIdx.x;
    uint4* bf = reinterpret_cast<uint4*>(&g_Bf[0][0][0]);
    if (i < 32768) bf[i] = make_uint4(0, 0, 0, 0);
    if (i < NCTA) g_arrive[i] = 0;
    if (i == 0) g_go = 0;
}

// ---------------- pack: recurrence W -> A-frag images (proven) ---------------
__global__ void pack_hmma(const float* __restrict__ W0, const float* __restrict__ W1,
                          const float* __restrict__ W2)
{
    unsigned id = blockIdx.x * blockDim.x + threadIdx.x;
    int reg = id & 3, lane = (id >> 2) & 31, tile = (id >> 7) & 7;
    int mh = (id >> 10) & 1, kc = (id >> 11) & 7;
    unsigned rm = id >> 14;
    int mat = rm % 3, cta = (int)(rm / 3);
    int r = lane >> 2, cq = (lane & 3) * 2;
    int m = mh * 16 + r + (reg & 1) * 8;
    int k = kc * 128 + tile * 16 + cq + ((reg >> 1) & 1) * 8;
    int col = (m >> 3) * Hh + cta * 8 + (m & 7);
    const float* W = (mat == 0) ? W0 : ((mat == 1) ? W1 : W2);
    unsigned hp, lp;
    split2(W[(size_t)k * Gg + col], W[(size_t)(k + 1) * Gg + col], hp, lp);
    int blk = (mat == 2) ? (16 + tile) : (tile * 2 + mat);
    size_t base = ((size_t)cta * 16 + (size_t)(kc * 2 + mh)) * 24576
                  + (size_t)blk * 1024 + (size_t)(lane * 32);
    *(unsigned*)(g_Wf + base + reg * 4) = hp;
    *(unsigned*)(g_Wf + base + 16 + reg * 4) = lp;
}

// ---------------- pack: GEMM B [K,N] fp32 -> B-frag hi|lo images -------------
__global__ void pack_Bw(const float* __restrict__ B, char* __restrict__ dst,
                        int KT, int N)
{
    unsigned id = blockIdx.x * blockDim.x + threadIdx.x;
    int reg = id & 1, lane = (id >> 1) & 31, n8 = (id >> 6) & 7;
    unsigned i9 = id >> 9;
    int kt = (int)(i9 % (unsigned)KT), nblk = (int)(i9 / (unsigned)KT);
    int n = nblk * 64 + n8 * 8 + (lane >> 2);
    int k = kt * 16 + reg * 8 + (lane & 3) * 2;
    unsigned hp, lp;
    split2(B[(size_t)k * N + n], B[(size_t)(k + 1) * N + n], hp, lp);
    size_t base = ((size_t)(nblk * KT + kt) * 8 + n8) * 512 + (size_t)(lane * 16);
    *(unsigned*)(dst + base + reg * 4) = hp;
    *(unsigned*)(dst + base + 8 + reg * 4) = lp;
}

// ---------------- cvt: A [M,K] fp32 -> A-frag hi|lo images -------------------
__global__ void cvt_Ax(const float* __restrict__ A, char* __restrict__ dst,
                       int KT, int K)
{
    unsigned id = blockIdx.x * blockDim.x + threadIdx.x;
    int reg = id & 3, lane = (id >> 2) & 31, mf = (id >> 7) & 7;
    unsigned i10 = id >> 10;
    int kt = (int)(i10 % (unsigned)KT), mblk = (int)(i10 / (unsigned)KT);
    int m = mblk * 128 + mf * 16 + (lane >> 2) + (reg & 1) * 8;
    int k = kt * 16 + (lane & 3) * 2 + ((reg >> 1) & 1) * 8;
    unsigned hp, lp;
    split2(A[(size_t)m * K + k], A[(size_t)m * K + k + 1], hp, lp);
    size_t base = ((size_t)(mblk * KT + kt) * 8 + mf) * 1024 + (size_t)(lane * 32);
    *(unsigned*)(dst + base + reg * 4) = hp;
    *(unsigned*)(dst + base + 16 + reg * 4) = lp;
}

// ---------------- HMMA GEMM: C[M,N] = A@B + bias (proven R15) ----------------
__global__ void __launch_bounds__(256) hmma_gemm(
        const char* __restrict__ Apk, const char* __restrict__ Bpk,
        const float* __restrict__ bias, float* __restrict__ C, int KT, int N)
{
    __shared__ char As[2][8192];
    __shared__ char Bs[2][4096];
    const int tid = threadIdx.x, lane = tid & 31, wid = tid >> 5;
    const int mw = wid & 3, nw = wid >> 2;
    const int mblk = blockIdx.y, nblk = blockIdx.x;
    const char* Agp = Apk + (size_t)mblk * KT * 8192;
    const char* Bgp = Bpk + (size_t)nblk * KT * 4096;
    const unsigned sa0 = smem_u32(As[0]), sa1 = smem_u32(As[1]);
    const unsigned sb0 = smem_u32(Bs[0]), sb1 = smem_u32(Bs[1]);

    float acc[2][4][4];
#pragma unroll
    for (int i = 0; i < 2; ++i)
#pragma unroll
        for (int j = 0; j < 4; ++j)
#pragma unroll
            for (int c = 0; c < 4; ++c) acc[i][j][c] = 0.f;

    cp16(sa0 + tid * 32, Agp + tid * 32);
    cp16(sa0 + tid * 32 + 16, Agp + tid * 32 + 16);
    cp16(sb0 + tid * 16, Bgp + tid * 16);
    CPC;

#pragma unroll 1
    for (int kt = 0; kt < KT; ++kt) {
        if (kt + 1 < KT) {
            unsigned da = (kt & 1) ? sa0 : sa1;
            unsigned db = (kt & 1) ? sb0 : sb1;
            const char* pa = Agp + (size_t)(kt + 1) * 8192;
            const char* pb = Bgp + (size_t)(kt + 1) * 4096;
            cp16(da + tid * 32, pa + tid * 32);
            cp16(da + tid * 32 + 16, pa + tid * 32 + 16);
            cp16(db + tid * 16, pb + tid * 16);
            CPC;
            CPW1;
        } else {
            CPW0;
        }
        __syncthreads();
        unsigned ab = (kt & 1) ? sa1 : sa0;
        unsigned bbs = (kt & 1) ? sb1 : sb0;
#pragma unroll
        for (int mi = 0; mi < 2; ++mi) {
            unsigned ah[4], al[4];
            ldsA(ab + (unsigned)((mw + mi * 4) * 1024 + lane * 32), ah, al);
#pragma unroll
            for (int n8 = 0; n8 < 4; ++n8) {
                unsigned bh0, bh1, bl0, bl1;
                asm volatile("ld.shared.v4.b32 {%0,%1,%2,%3},[%4];"
                    : "=r"(bh0), "=r"(bh1), "=r"(bl0), "=r"(bl1)
                    : "r"(bbs + (unsigned)((nw * 4 + n8) * 512 + lane * 16)));
                mmabf(acc[mi][n8], ah, bh0, bh1);
                mmabf(acc[mi][n8], al, bh0, bh1);
                mmabf(acc[mi][n8], ah, bl0, bl1);
            }
        }
        __syncthreads();
    }

#pragma unroll
    for (int mi = 0; mi < 2; ++mi) {
        int m0 = mblk * 128 + (mw + mi * 4) * 16 + (lane >> 2);
#pragma unroll
        for (int n8 = 0; n8 < 4; ++n8) {
            int n0 = nblk * 64 + (nw * 4 + n8) * 8 + (lane & 3) * 2;
            float2 bv = *reinterpret_cast<const float2*>(&bias[n0]);
            *reinterpret_cast<float2*>(&C[(size_t)m0 * N + n0]) =
                make_float2(acc[mi][n8][0] + bv.x, acc[mi][n8][1] + bv.y);
            *reinterpret_cast<float2*>(&C[(size_t)(m0 + 8) * N + n0]) =
                make_float2(acc[mi][n8][2] + bv.x, acc[mi][n8][3] + bv.y);
        }
    }
}

__device__ __forceinline__ void grid_bar(unsigned target) {
    __syncthreads();
    const unsigned tid = threadIdx.x;
    if (tid == 0) { __threadfence(); st_rel(&g_arrive[blockIdx.x], target); }
    if (blockIdx.x == 0) {
        if (tid < NCTA) { while (ld_acq(&g_arrive[tid]) < target) {} }
        __syncthreads();
        if (tid == 0) st_rel(&g_go, target);
    }
    if (tid == 0) { while (ld_acq(&g_go) < target) {} }
    __syncthreads();
}

// ---------------- recurrence pieces -------------------------------------------
// stage THIS pair's 16KB slice of one h-frag buffer (16 cp16/thread, 1 group)
__device__ __forceinline__ void stage_slice(unsigned sb, const char* src,
                                            unsigned slice, int lt)
{
    const char* sp = src + slice;
#pragma unroll
    for (int i = 0; i < 16; ++i) {
        unsigned o = (unsigned)((i * 64 + lt) * 16);
        cp16(sb + slice + o, sp + o);
    }
    CPC;
}

__device__ __forceinline__ void run_fused(float (&acc)[4][4], float (&accB)[4][4],
    bool a0, bool a1, int &cb, unsigned wring, const char* __restrict__ wg,
    unsigned sb, int kc, int lane)
{
    unsigned bf[4][4];
#pragma unroll 1
    for (int blk = 0; blk < 16; ++blk) {
        int pb = cb + 2; if (pb >= 24) pb -= 24;
        wpf(wring + (unsigned)((pb % 3) * 1024), wg + (size_t)pb * 1024, lane);
        CPW2;
        __syncwarp();
        int kt = kc * 8 + (blk >> 1);
        unsigned sa = wring + (unsigned)((cb % 3) * 1024 + lane * 32);
        if ((blk & 1) == 0) {
            if (a0 | a1) {
#pragma unroll
                for (int n8 = 0; n8 < 4; ++n8)
                    asm volatile("ld.shared.v4.b32 {%0,%1,%2,%3},[%4];"
                        : "=r"(bf[n8][0]), "=r"(bf[n8][1]),
                          "=r"(bf[n8][2]), "=r"(bf[n8][3])
                        : "r"(sb + (unsigned)(((kt * 4 + n8) * 32 + lane) * 16)));
            }
            if (a0) {
                unsigned ah[4], al[4];
                ldsA(sa, ah, al);
#pragma unroll
                for (int n8 = 0; n8 < 4; ++n8) {
                    mmabf(acc[n8], ah, bf[n8][0], bf[n8][1]);
                    mmabf(acc[n8], al, bf[n8][0], bf[n8][1]);
                    mmabf(acc[n8], ah, bf[n8][2], bf[n8][3]);
                }
            }
        } else if (a1) {
            unsigned ah[4], al[4];
            ldsA(sa, ah, al);
#pragma unroll
            for (int n8 = 0; n8 < 4; ++n8) {
                mmabf(accB[n8], ah, bf[n8][0], bf[n8][1]);
                mmabf(accB[n8], al, bf[n8][0], bf[n8][1]);
                mmabf(accB[n8], ah, bf[n8][2], bf[n8][3]);
            }
        }
        ++cb; if (cb >= 24) cb = 0;
    }
}

// mat2: uniform pipeline (B-h1 visibility guaranteed by block sync before call)
__device__ __forceinline__ void run_mat2(float (&accB)[4][4], bool a2, int &cb,
    unsigned wring, const char* __restrict__ wg, unsigned sb, int kc, int lane)
{
#pragma unroll 1
    for (int tile = 0; tile < 8; ++tile) {
        int pb = cb + 2; if (pb >= 24) pb -= 24;
        wpf(wring + (unsigned)((pb % 3) * 1024), wg + (size_t)pb * 1024, lane);
        CPW2;
        __syncwarp();
        if (a2) {
            int kt = kc * 8 + tile;
            unsigned sa = wring + (unsigned)((cb % 3) * 1024 + lane * 32);
            unsigned ah[4], al[4];
            ldsA(sa, ah, al);
#pragma unroll
            for (int n8 = 0; n8 < 4; ++n8) {
                unsigned b0, b1, b2, b3;
                asm volatile("ld.shared.v4.b32 {%0,%1,%2,%3},[%4];"
                    : "=r"(b0), "=r"(b1), "=r"(b2), "=r"(b3)
                    : "r"(sb + (unsigned)(((kt * 4 + n8) * 32 + lane) * 16)));
                mmabf(accB[n8], ah, b0, b1);
                mmabf(accB[n8], al, b0, b1);
                mmabf(accB[n8], ah, b2, b3);
            }
        }
        ++cb; if (cb >= 24) cb = 0;
    }
}

__device__ __forceinline__ void store_redH(float* red, float (&acc)[4][4],
                                           int kc, int mh, int lane)
{
    int r = lane >> 2, cq = (lane & 3) * 2;
#pragma unroll
    for (int n8 = 0; n8 < 4; ++n8) {
        int b = n8 * 8 + cq;
        int c = mh * 16 + r;
        *reinterpret_cast<float2*>(&red[kc * 1152 + c * 36 + b]) =
            make_float2(acc[n8][0], acc[n8][1]);
        *reinterpret_cast<float2*>(&red[kc * 1152 + (c + 8) * 36 + b]) =
            make_float2(acc[n8][2], acc[n8][3]);
    }
}

__device__ __forceinline__ void wr_frag(char* bb, int k, int b, float h) {
    int kt = k >> 4, kin = k & 15;
    int reg = kin >> 3, quad = (kin >> 1) & 3, half = kin & 1;
    unsigned off = (unsigned)((((kt * 4 + (b >> 3)) * 32) + (b & 7) * 4 + quad) * 16
                              + reg * 4 + half * 2);
    __nv_bfloat16 hh = __float2bfloat16(h);
    __nv_bfloat16 hl = __float2bfloat16(h - __bfloat162float(hh));
    *(__nv_bfloat16*)(bb + off) = hh;
    *(__nv_bfloat16*)(bb + off + 8) = hl;
}

__device__ __forceinline__ void wr_Ypk(int m, int k, float h) {
    int mblk = m >> 7, mi = m & 127, mf = mi >> 4, r16 = mi & 15;
    int kt = k >> 4, ki = k & 15;
    int reg = (r16 >> 3) | ((ki >> 3) << 1);
    int ln = (r16 & 7) * 4 + ((ki & 7) >> 1);
    size_t base = ((size_t)(mblk * 64 + kt) * 8 + mf) * 1024 + (size_t)(ln * 32);
    __nv_bfloat16 hh = __float2bfloat16(h);
    __nv_bfloat16 hl = __float2bfloat16(h - __bfloat162float(hh));
    char* p = g_Ypk + base + reg * 4 + (ki & 1) * 2;
    *(__nv_bfloat16*)p = hh;
    *(__nv_bfloat16*)(p + 16) = hl;
}

// ---------------- persistent 2-layer LSTM recurrence (HMMA, pair-staged) -----
__global__ void __launch_bounds__(512, 1) lstm_hm3(const float* __restrict__ b1v)
{
    extern __shared__ char smc[];
    float* red = reinterpret_cast<float*>(smc + 180224);
    const unsigned sb = smem_u32(smc);

    const int tid = threadIdx.x, lane = tid & 31, wid = tid >> 5;
    const int kc = wid >> 1, mh = wid & 1;
    const int lt = tid & 63;                        // thread-in-pair
    const unsigned slice = (unsigned)(kc * 16384);  // pair's B slice
    const int cta = blockIdx.x, jbase = cta * 8;
    const unsigned wring = sb + 131072u + (unsigned)(wid * 3072);
    const char* wg = g_Wf + ((size_t)cta * 16 + (size_t)(kc * 2 + mh)) * 24576;

    const int gb = tid >> 3, gj = tid & 7;
    float c0s = 0.f, c1s = 0.f;
    float bias1[4];
    if (tid < 256) {
#pragma unroll
        for (int g = 0; g < 4; ++g) bias1[g] = b1v[g * Hh + jbase + gj];
    }

    int cb = 0;
    wpf(wring, wg, lane);
    wpf(wring + 1024, wg + 1024, lane);

    for (int s = 0; s <= Tt; ++s) {
        const int rb = (s + 1) & 1;
        const int wb = s & 1;

        stage_slice(sb, g_Bf[0][rb], slice, lt);     // own h0 slice only

        float xw[4];                                  // hidden under slice wait
        if (tid < 256 && s < Tt) {
#pragma unroll
            for (int g = 0; g < 4; ++g)
                xw[g] = __ldcg(&g_XW[((size_t)gb * Tt + s) * Gg + g * Hh + jbase + gj]);
        }
        CPW0;
        PAIRBAR(kc + 1);

        float acc[4][4], accB[4][4];
#pragma unroll
        for (int i = 0; i < 4; ++i)
#pragma unroll
            for (int j = 0; j < 4; ++j) { acc[i][j] = 0.f; accB[i][j] = 0.f; }

        run_fused(acc, accB, s < Tt, s > 0, cb, wring, wg, sb, kc, lane);
        if (s < Tt) store_redH(red, acc, kc, mh, lane);
        __syncthreads();                              // #1: red ready, B(h0) free

        stage_slice(sb, g_Bf[1][rb], slice, lt);      // issue h1 slice

        float z0[4];                                  // reduction hides h1 latency
        if (tid < 256 && s < Tt) {
#pragma unroll
            for (int g = 0; g < 4; ++g) {
                float t = xw[g];
#pragma unroll
                for (int kk = 0; kk < 8; ++kk)
                    t += red[kk * 1152 + (g * 8 + gj) * 36 + gb];
                z0[g] = t;
            }
        }
        CPW0;
        __syncthreads();                              // #2: slices visible, z0 read

        run_mat2(accB, s > 0, cb, wring, wg, sb, kc, lane);
        if (s > 0) store_redH(red, accB, kc, mh, lane);
        __syncthreads();                              // #3: red(mat2) ready

        if (tid < 256) {
            if (s < Tt) {
                float I = sig_(z0[0]), F = sig_(z0[1]);
                float G = tanh_(z0[2]), O = sig_(z0[3]);
                c0s = F * c0s + I * G;
                float h = O * tanh_(c0s);
                wr_frag(g_Bf[0][wb], jbase + gj, gb, h);
            }
            if (s > 0) {
                float z1[4];
#pragma unroll
                for (int g = 0; g < 4; ++g) {
                    float t = bias1[g];
#pragma unroll
                    for (int kk = 0; kk < 8; ++kk)
                        t += red[kk * 1152 + (g * 8 + gj) * 36 + gb];
                    z1[g] = t;
                }
                float I = sig_(z1[0]), F = sig_(z1[1]);
                float G = tanh_(z1[2]), O = sig_(z1[3]);
                c1s = F * c1s + I * G;
                float h = O * tanh_(c1s);
                wr_frag(g_Bf[1][wb], jbase + gj, gb, h);
                wr_Ypk(gb * Tt + (s - 1), jbase + gj, h);
            }
        }
        grid_bar((unsigned)(s + 1));
    }
    CPW0;
}

// ---------------- launch ------------------------------------------------------
extern "C" void kernel_launch(void* const* d_in, const int* in_sizes, int n_in,
                              void* d_out, int out_size)
{
    const float* x   = (const float*)d_in[0];
    const float* Wx0 = (const float*)d_in[1];
    const float* Wh0 = (const float*)d_in[2];
    const float* b0v = (const float*)d_in[3];
    const float* Wx1 = (const float*)d_in[4];
    const float* Wh1 = (const float*)d_in[5];
    const float* b1v = (const float*)d_in[6];
    const float* Wd  = (const float*)d_in[7];
    const float* bdv = (const float*)d_in[8];
    float* out = (float*)d_out;

    float* xw;  cudaGetSymbolAddress((void**)&xw,  g_XW);
    char*  apx; cudaGetSymbolAddress((void**)&apx, g_Apx);
    char*  ypk; cudaGetSymbolAddress((void**)&ypk, g_Ypk);
    char*  bx;  cudaGetSymbolAddress((void**)&bx,  g_Bx);
    char*  bd;  cudaGetSymbolAddress((void**)&bd,  g_Bd);

    cudaFuncSetAttribute(lstm_hm3, cudaFuncAttributeMaxDynamicSharedMemorySize, SMT);

    init_state<<<64, 512>>>();
    pack_hmma<<<24576, 256>>>(Wh0, Wx1, Wh1);
    pack_Bw<<<4096, 256>>>(Wx0, bx, Dd / 16, Gg);
    pack_Bw<<<1024, 256>>>(Wd,  bd, Hh / 16, Oo);
    cvt_Ax<<<16384, 256>>>(x, apx, Dd / 16, Dd);

    // XW = x @ Wx0 + b0   [16384,4096]
    hmma_gemm<<<dim3(Gg / 64, (Bb * Tt) / 128), 256>>>(apx, bx, b0v, xw,
                                                       Dd / 16, Gg);
    lstm_hm3<<<NCTA, 512, SMT>>>(b1v);

    // out = Y @ Wd + bd   [16384,512]
    hmma_gemm<<<dim3(Oo / 64, (Bb * Tt) / 128), 256>>>(ypk, bd, bdv, out,
                                                       Hh / 16, Oo);
}